// round 2
// baseline (speedup 1.0000x reference)
#include <cuda_runtime.h>
#include <math.h>

typedef unsigned long long u64;

#define Nn 8192
#define Dd 64
#define NCH 64          // 8192 / 128 tile chunks per dimension

// ---------------- scratch (static device memory; no allocations) ----------------
__device__ float d_Cxy[(u64)Nn * Nn];
__device__ float d_Cxx[(u64)Nn * Nn];
__device__ float d_Cyy[(u64)Nn * Nn];
__device__ float d_sqx[Nn], d_sqy[Nn];
__device__ float d_faa[Nn], d_gbb[Nn], d_gab[Nn], d_fba[Nn];
__device__ float d_tft[Nn], d_tgt[Nn], d_tftaa[Nn], d_tgtbb[Nn];
__device__ float d_pRowM[(u64)NCH * Nn], d_pRowS[(u64)NCH * Nn];
__device__ float d_pColM[(u64)NCH * Nn], d_pColS[(u64)NCH * Nn];

// ---------------- 0.5*||row||^2 ----------------
__global__ void sqnorm_kernel(const float* __restrict__ X, float* __restrict__ sq) {
    int gw   = (blockIdx.x * blockDim.x + threadIdx.x) >> 5;
    int lane = threadIdx.x & 31;
    if (gw >= Nn) return;
    const float* xr = X + (u64)gw * Dd;
    float a = xr[lane], b = xr[lane + 32];
    float s = a * a + b * b;
    #pragma unroll
    for (int o = 16; o; o >>= 1) s += __shfl_xor_sync(0xffffffffu, s, o);
    if (lane == 0) sq[gw] = 0.5f * s;
}

// ---------------- C[i][j] = max(0.5|a_i|^2 + 0.5|b_j|^2 - a_i.b_j, 0) ----------------
__global__ void __launch_bounds__(256, 2) cost_gemm_kernel(
    const float* __restrict__ A, const float* __restrict__ B,
    const float* __restrict__ sqa, const float* __restrict__ sqb,
    float* __restrict__ C)
{
    __shared__ float As[32][128];
    __shared__ float Bs[32][128];
    const int bi  = blockIdx.y * 128;
    const int bj  = blockIdx.x * 128;
    const int tid = threadIdx.x;
    const int tx  = tid & 15, ty = tid >> 4;

    float acc[8][8];
    #pragma unroll
    for (int r = 0; r < 8; ++r)
        #pragma unroll
        for (int c = 0; c < 8; ++c) acc[r][c] = 0.f;

    for (int kc = 0; kc < Dd; kc += 32) {
        #pragma unroll
        for (int it = 0; it < 4; ++it) {
            int idx = tid + it * 256;
            int row = idx >> 3;
            int kq  = idx & 7;
            float4 a = *(const float4*)(A + (u64)(bi + row) * Dd + kc + kq * 4);
            float4 b = *(const float4*)(B + (u64)(bj + row) * Dd + kc + kq * 4);
            As[kq * 4 + 0][row] = a.x; As[kq * 4 + 1][row] = a.y;
            As[kq * 4 + 2][row] = a.z; As[kq * 4 + 3][row] = a.w;
            Bs[kq * 4 + 0][row] = b.x; Bs[kq * 4 + 1][row] = b.y;
            Bs[kq * 4 + 2][row] = b.z; Bs[kq * 4 + 3][row] = b.w;
        }
        __syncthreads();
        #pragma unroll
        for (int k = 0; k < 32; ++k) {
            float4 a0 = *(const float4*)&As[k][ty * 4];
            float4 a1 = *(const float4*)&As[k][64 + ty * 4];
            float4 b0 = *(const float4*)&Bs[k][tx * 4];
            float4 b1 = *(const float4*)&Bs[k][64 + tx * 4];
            float av[8] = {a0.x, a0.y, a0.z, a0.w, a1.x, a1.y, a1.z, a1.w};
            float bv[8] = {b0.x, b0.y, b0.z, b0.w, b1.x, b1.y, b1.z, b1.w};
            #pragma unroll
            for (int r = 0; r < 8; ++r)
                #pragma unroll
                for (int c = 0; c < 8; ++c)
                    acc[r][c] = fmaf(av[r], bv[c], acc[r][c]);
        }
        __syncthreads();
    }

    #pragma unroll
    for (int rg = 0; rg < 2; ++rg)
        #pragma unroll
        for (int q = 0; q < 4; ++q) {
            int i = bi + rg * 64 + ty * 4 + q;
            float sa = sqa[i];
            int r = rg * 4 + q;
            #pragma unroll
            for (int cg = 0; cg < 2; ++cg) {
                int j0 = bj + cg * 64 + tx * 4;
                float4 v;
                v.x = fmaxf(sa + sqb[j0 + 0] - acc[r][cg * 4 + 0], 0.f);
                v.y = fmaxf(sa + sqb[j0 + 1] - acc[r][cg * 4 + 1], 0.f);
                v.z = fmaxf(sa + sqb[j0 + 2] - acc[r][cg * 4 + 2], 0.f);
                v.w = fmaxf(sa + sqb[j0 + 3] - acc[r][cg * 4 + 3], 0.f);
                *(float4*)(C + (u64)i * Nn + j0) = v;
            }
        }
}

// ---------------- fused row+col softmin over Cxy (one matrix read per iteration) -------
// 128x128 tile / block. Row-dir potential = gab (over cols), col-dir potential = fba.
// Writes per-tile LSE partials (m, s); combined by combine_kernel.
// SMEM layout uses group rotation (g + r) & 31 so float4 LDS/STS are conflict-free
// in both the row phase and the column phase.
__global__ void __launch_bounds__(256) fused_xy_kernel(
    const float* __restrict__ C, const float* __restrict__ fba, const float* __restrict__ gab,
    const float* __restrict__ eps_ptr, float base, int init,
    float* __restrict__ pRowM, float* __restrict__ pRowS,
    float* __restrict__ pColM, float* __restrict__ pColS)
{
    __shared__ float tile[128 * 128];
    __shared__ float fpot[128];   // base + fba[i]/eps   (col direction)
    __shared__ float gpot[128];   // base + gab[j]/eps   (row direction)

    const int tid = threadIdx.x, lane = tid & 31, w = tid >> 5;
    const float inv = 1.0f / (*eps_ptr);
    const int bi = blockIdx.y * 128;
    const int bj = blockIdx.x * 128;

    if (tid < 128) {
        fpot[tid] = init ? base : fmaf(fba[bi + tid], inv, base);
        gpot[tid] = init ? base : fmaf(gab[bj + tid], inv, base);
    }

    // load + scale tile: w = C * inv_eps
    #pragma unroll
    for (int k = 0; k < 16; ++k) {
        int r = k * 8 + w;
        float4 c4 = *(const float4*)(C + (u64)(bi + r) * Nn + bj + 4 * lane);
        int grp = (lane + r) & 31;
        float4 wv;
        wv.x = c4.x * inv; wv.y = c4.y * inv; wv.z = c4.z * inv; wv.w = c4.w * inv;
        *(float4*)&tile[r * 128 + grp * 4] = wv;
    }
    __syncthreads();

    // ---- row phase: warp handles rows w, w+8, ..., w+120 ----
    {
        float4 gp = *(const float4*)&gpot[lane * 4];
        #pragma unroll
        for (int rr = 0; rr < 16; ++rr) {
            int r = w + rr * 8;
            int grp = (lane + r) & 31;
            float4 wv = *(const float4*)&tile[r * 128 + grp * 4];
            float v0 = gp.x - wv.x, v1 = gp.y - wv.y, v2 = gp.z - wv.z, v3 = gp.w - wv.w;
            float m = fmaxf(fmaxf(v0, v1), fmaxf(v2, v3));
            #pragma unroll
            for (int o = 16; o; o >>= 1) m = fmaxf(m, __shfl_xor_sync(0xffffffffu, m, o));
            float s = __expf(v0 - m) + __expf(v1 - m) + __expf(v2 - m) + __expf(v3 - m);
            #pragma unroll
            for (int o = 16; o; o >>= 1) s += __shfl_xor_sync(0xffffffffu, s, o);
            if (lane == 0) {
                pRowM[(u64)blockIdx.x * Nn + bi + r] = m;
                pRowS[(u64)blockIdx.x * Nn + bi + r] = s;
            }
        }
    }

    // ---- col phase: warp handles col groups 4w..4w+3 (16 columns) ----
    #pragma unroll
    for (int gi = 0; gi < 4; ++gi) {
        int g = w * 4 + gi;          // columns 4g .. 4g+3
        float vals[16];
        #pragma unroll
        for (int k = 0; k < 4; ++k) {
            int r = lane + 32 * k;
            int grp = (g + r) & 31;
            float4 wv = *(const float4*)&tile[r * 128 + grp * 4];
            float fp = fpot[r];
            vals[k * 4 + 0] = fp - wv.x;
            vals[k * 4 + 1] = fp - wv.y;
            vals[k * 4 + 2] = fp - wv.z;
            vals[k * 4 + 3] = fp - wv.w;
        }
        float m[4], s[4];
        #pragma unroll
        for (int e = 0; e < 4; ++e)
            m[e] = fmaxf(fmaxf(vals[e], vals[4 + e]), fmaxf(vals[8 + e], vals[12 + e]));
        #pragma unroll
        for (int o = 16; o; o >>= 1) {
            #pragma unroll
            for (int e = 0; e < 4; ++e)
                m[e] = fmaxf(m[e], __shfl_xor_sync(0xffffffffu, m[e], o));
        }
        #pragma unroll
        for (int e = 0; e < 4; ++e)
            s[e] = __expf(vals[e] - m[e]) + __expf(vals[4 + e] - m[e]) +
                   __expf(vals[8 + e] - m[e]) + __expf(vals[12 + e] - m[e]);
        #pragma unroll
        for (int o = 16; o; o >>= 1) {
            #pragma unroll
            for (int e = 0; e < 4; ++e)
                s[e] += __shfl_xor_sync(0xffffffffu, s[e], o);
        }
        if (lane == 0) {
            #pragma unroll
            for (int e = 0; e < 4; ++e) {
                pColM[(u64)blockIdx.y * Nn + bj + 4 * g + e] = m[e];
                pColS[(u64)blockIdx.y * Nn + bj + 4 * g + e] = s[e];
            }
        }
    }
}

// ---------------- combine NCH per-tile LSE partials into final softmin ----------------
__global__ void __launch_bounds__(256) combine_kernel(
    const float* __restrict__ pM, const float* __restrict__ pS,
    const float* __restrict__ eps_ptr, float* __restrict__ out)
{
    int i = blockIdx.x * 256 + threadIdx.x;
    float eps = *eps_ptr;
    float M = -3.4e38f;
    #pragma unroll 8
    for (int c = 0; c < NCH; ++c) M = fmaxf(M, pM[(u64)c * Nn + i]);
    float S = 0.f;
    #pragma unroll 8
    for (int c = 0; c < NCH; ++c)
        S += pS[(u64)c * Nn + i] * __expf(pM[(u64)c * Nn + i] - M);
    out[i] = -eps * (logf(S) + M);
}

// ---------------- single-pass register-resident row softmin (Cxx / Cyy) ----------------
__global__ void __launch_bounds__(256) rowsoftmin_kernel(
    const float* __restrict__ C, const float* __restrict__ pot,
    const float* __restrict__ eps_ptr, float base, int init, float* __restrict__ out)
{
    __shared__ float redA[8];
    __shared__ float redB[8];
    const int tid = threadIdx.x, lane = tid & 31, wid = tid >> 5;
    const float eps = *eps_ptr;
    const float inv = 1.0f / eps;
    const float* Cr = C + (u64)blockIdx.x * Nn;

    float v[32];
    #pragma unroll
    for (int c = 0; c < 8; ++c) {
        int j = (c << 10) + (tid << 2);
        float4 cc = *(const float4*)(Cr + j);
        if (init) {
            v[c * 4 + 0] = fmaf(cc.x, -inv, base);
            v[c * 4 + 1] = fmaf(cc.y, -inv, base);
            v[c * 4 + 2] = fmaf(cc.z, -inv, base);
            v[c * 4 + 3] = fmaf(cc.w, -inv, base);
        } else {
            float4 p = *(const float4*)(pot + j);
            v[c * 4 + 0] = fmaf(p.x - cc.x, inv, base);
            v[c * 4 + 1] = fmaf(p.y - cc.y, inv, base);
            v[c * 4 + 2] = fmaf(p.z - cc.z, inv, base);
            v[c * 4 + 3] = fmaf(p.w - cc.w, inv, base);
        }
    }
    float m = v[0];
    #pragma unroll
    for (int k = 1; k < 32; ++k) m = fmaxf(m, v[k]);
    #pragma unroll
    for (int o = 16; o; o >>= 1) m = fmaxf(m, __shfl_xor_sync(0xffffffffu, m, o));
    if (lane == 0) redA[wid] = m;
    __syncthreads();
    float M = redA[0];
    #pragma unroll
    for (int i = 1; i < 8; ++i) M = fmaxf(M, redA[i]);

    float s = 0.f;
    #pragma unroll
    for (int k = 0; k < 32; ++k) s += __expf(v[k] - M);
    #pragma unroll
    for (int o = 16; o; o >>= 1) s += __shfl_xor_sync(0xffffffffu, s, o);
    if (lane == 0) redB[wid] = s;
    __syncthreads();
    if (tid == 0) {
        float S = 0.f;
        #pragma unroll
        for (int i = 0; i < 8; ++i) S += redB[i];
        out[blockIdx.x] = -eps * (logf(S) + M);
    }
}

// ---------------- symmetrized dual update ----------------
__global__ void update_kernel(const float* __restrict__ tftaa, const float* __restrict__ tgtbb,
                              const float* __restrict__ tgt, const float* __restrict__ tft,
                              float* __restrict__ faa, float* __restrict__ gbb,
                              float* __restrict__ gab, float* __restrict__ fba)
{
    int i = blockIdx.x * blockDim.x + threadIdx.x;
    faa[i] = 0.5f * (faa[i] + tftaa[i]);
    gbb[i] = 0.5f * (gbb[i] + tgtbb[i]);
    gab[i] = 0.5f * (gab[i] + tgt[i]);
    fba[i] = 0.5f * (fba[i] + tft[i]);
}

// ---------------- final scalar ----------------
__global__ void final_kernel(const float* __restrict__ fbaf, const float* __restrict__ faaf,
                             const float* __restrict__ gabf, const float* __restrict__ gbbf,
                             float* __restrict__ out)
{
    __shared__ float red[32];
    int tid = threadIdx.x;
    int lane = tid & 31, wid = tid >> 5;
    float s = 0.f;
    for (int i = tid; i < Nn; i += 1024)
        s += (fbaf[i] - faaf[i]) + (gabf[i] - gbbf[i]);
    #pragma unroll
    for (int o = 16; o; o >>= 1) s += __shfl_xor_sync(0xffffffffu, s, o);
    if (lane == 0) red[wid] = s;
    __syncthreads();
    if (wid == 0) {
        float v = red[lane];
        #pragma unroll
        for (int o = 16; o; o >>= 1) v += __shfl_xor_sync(0xffffffffu, v, o);
        if (lane == 0) out[0] = v / (float)Nn;
    }
}

// ---------------- launch ----------------
extern "C" void kernel_launch(void* const* d_in, const int* in_sizes, int n_in,
                              void* d_out, int out_size)
{
    const float* X   = (const float*)d_in[0];
    const float* Y   = (const float*)d_in[1];
    const float* eps = (const float*)d_in[2];
    const int n_eps  = in_sizes[2];
    float* out = (float*)d_out;

    float *Cxy, *Cxx, *Cyy, *sqx, *sqy;
    float *faa, *gbb, *gab, *fba, *tft, *tgt, *tftaa, *tgtbb;
    float *pRowM, *pRowS, *pColM, *pColS;
    cudaGetSymbolAddress((void**)&Cxy, d_Cxy);
    cudaGetSymbolAddress((void**)&Cxx, d_Cxx);
    cudaGetSymbolAddress((void**)&Cyy, d_Cyy);
    cudaGetSymbolAddress((void**)&sqx, d_sqx);
    cudaGetSymbolAddress((void**)&sqy, d_sqy);
    cudaGetSymbolAddress((void**)&faa, d_faa);
    cudaGetSymbolAddress((void**)&gbb, d_gbb);
    cudaGetSymbolAddress((void**)&gab, d_gab);
    cudaGetSymbolAddress((void**)&fba, d_fba);
    cudaGetSymbolAddress((void**)&tft, d_tft);
    cudaGetSymbolAddress((void**)&tgt, d_tgt);
    cudaGetSymbolAddress((void**)&tftaa, d_tftaa);
    cudaGetSymbolAddress((void**)&tgtbb, d_tgtbb);
    cudaGetSymbolAddress((void**)&pRowM, d_pRowM);
    cudaGetSymbolAddress((void**)&pRowS, d_pRowS);
    cudaGetSymbolAddress((void**)&pColM, d_pColM);
    cudaGetSymbolAddress((void**)&pColS, d_pColS);

    const float LOGW = -logf((float)Nn);
    dim3 gg(Nn / 128, Nn / 128);
    dim3 gf(NCH, NCH);

    sqnorm_kernel<<<1024, 256>>>(X, sqx);
    sqnorm_kernel<<<1024, 256>>>(Y, sqy);
    cost_gemm_kernel<<<gg, 256>>>(X, Y, sqx, sqy, Cxy);
    cost_gemm_kernel<<<gg, 256>>>(X, X, sqx, sqx, Cxx);
    cost_gemm_kernel<<<gg, 256>>>(Y, Y, sqy, sqy, Cyy);

    // init at eps0
    fused_xy_kernel<<<gf, 256>>>(Cxy, nullptr, nullptr, eps, LOGW, 1,
                                 pRowM, pRowS, pColM, pColS);
    combine_kernel<<<Nn / 256, 256>>>(pRowM, pRowS, eps, fba);
    combine_kernel<<<Nn / 256, 256>>>(pColM, pColS, eps, gab);
    rowsoftmin_kernel<<<Nn, 256>>>(Cxx, nullptr, eps, LOGW, 1, faa);
    rowsoftmin_kernel<<<Nn, 256>>>(Cyy, nullptr, eps, LOGW, 1, gbb);

    // annealed symmetric Sinkhorn scan
    for (int k = 0; k < n_eps; ++k) {
        const float* ek = eps + k;
        fused_xy_kernel<<<gf, 256>>>(Cxy, fba, gab, ek, LOGW, 0,
                                     pRowM, pRowS, pColM, pColS);
        combine_kernel<<<Nn / 256, 256>>>(pRowM, pRowS, ek, tft);
        combine_kernel<<<Nn / 256, 256>>>(pColM, pColS, ek, tgt);
        rowsoftmin_kernel<<<Nn, 256>>>(Cxx, faa, ek, LOGW, 0, tftaa);
        rowsoftmin_kernel<<<Nn, 256>>>(Cyy, gbb, ek, LOGW, 0, tgtbb);
        update_kernel<<<Nn / 256, 256>>>(tftaa, tgtbb, tgt, tft, faa, gbb, gab, fba);
    }

    // final extrapolation at eps = blur^p
    const float* el = eps + (n_eps - 1);
    fused_xy_kernel<<<gf, 256>>>(Cxy, fba, gab, el, LOGW, 0,
                                 pRowM, pRowS, pColM, pColS);
    combine_kernel<<<Nn / 256, 256>>>(pRowM, pRowS, el, tft);   // f_ba_f
    combine_kernel<<<Nn / 256, 256>>>(pColM, pColS, el, tgt);   // g_ab_f
    rowsoftmin_kernel<<<Nn, 256>>>(Cxx, faa, el, LOGW, 0, tftaa); // f_aa_f
    rowsoftmin_kernel<<<Nn, 256>>>(Cyy, gbb, el, LOGW, 0, tgtbb); // g_bb_f

    final_kernel<<<1, 1024>>>(tft, tftaa, tgt, tgtbb, out);
}

// round 3
// speedup vs baseline: 1.0779x; 1.0779x over previous
#include <cuda_runtime.h>
#include <math.h>

typedef unsigned long long u64;

#define Nn 8192
#define Dd 64
#define NCH 64          // 8192/128 column chunks

// ---------------- scratch (static device memory; no allocations) ----------------
__device__ float d_Cxy[(u64)Nn * Nn];
__device__ float d_Cxx[(u64)Nn * Nn];   // lower triangle (block granularity) valid
__device__ float d_Cyy[(u64)Nn * Nn];   // lower triangle valid
__device__ float d_sqx[Nn], d_sqy[Nn];
__device__ float d_faa[Nn], d_gbb[Nn], d_gab[Nn], d_fba[Nn];
__device__ float d_tft[Nn], d_tgt[Nn], d_tftaa[Nn], d_tgtbb[Nn];
__device__ float d_pRM[(u64)NCH * Nn], d_pRS[(u64)NCH * Nn];
__device__ float d_pCM[(u64)NCH * Nn], d_pCS[(u64)NCH * Nn];

// ---------------- 0.5*||row||^2 ----------------
__global__ void sqnorm_kernel(const float* __restrict__ X, float* __restrict__ sq) {
    int gw   = (blockIdx.x * blockDim.x + threadIdx.x) >> 5;
    int lane = threadIdx.x & 31;
    if (gw >= Nn) return;
    const float* xr = X + (u64)gw * Dd;
    float a = xr[lane], b = xr[lane + 32];
    float s = a * a + b * b;
    #pragma unroll
    for (int o = 16; o; o >>= 1) s += __shfl_xor_sync(0xffffffffu, s, o);
    if (lane == 0) sq[gw] = 0.5f * s;
}

// ---------------- C[i][j] = max(0.5|a|^2 + 0.5|b|^2 - a.b, 0) ----------------
// sym != 0: only emit lower-triangle tiles (blockIdx.y >= blockIdx.x)
__global__ void __launch_bounds__(256, 2) cost_gemm_kernel(
    const float* __restrict__ A, const float* __restrict__ B,
    const float* __restrict__ sqa, const float* __restrict__ sqb,
    float* __restrict__ C, int sym)
{
    if (sym && blockIdx.y < blockIdx.x) return;
    __shared__ float As[32][128];
    __shared__ float Bs[32][128];
    const int bi  = blockIdx.y * 128;
    const int bj  = blockIdx.x * 128;
    const int tid = threadIdx.x;
    const int tx  = tid & 15, ty = tid >> 4;

    float acc[8][8];
    #pragma unroll
    for (int r = 0; r < 8; ++r)
        #pragma unroll
        for (int c = 0; c < 8; ++c) acc[r][c] = 0.f;

    for (int kc = 0; kc < Dd; kc += 32) {
        #pragma unroll
        for (int it = 0; it < 4; ++it) {
            int idx = tid + it * 256;
            int row = idx >> 3;
            int kq  = idx & 7;
            float4 a = *(const float4*)(A + (u64)(bi + row) * Dd + kc + kq * 4);
            float4 b = *(const float4*)(B + (u64)(bj + row) * Dd + kc + kq * 4);
            As[kq * 4 + 0][row] = a.x; As[kq * 4 + 1][row] = a.y;
            As[kq * 4 + 2][row] = a.z; As[kq * 4 + 3][row] = a.w;
            Bs[kq * 4 + 0][row] = b.x; Bs[kq * 4 + 1][row] = b.y;
            Bs[kq * 4 + 2][row] = b.z; Bs[kq * 4 + 3][row] = b.w;
        }
        __syncthreads();
        #pragma unroll
        for (int k = 0; k < 32; ++k) {
            float4 a0 = *(const float4*)&As[k][ty * 4];
            float4 a1 = *(const float4*)&As[k][64 + ty * 4];
            float4 b0 = *(const float4*)&Bs[k][tx * 4];
            float4 b1 = *(const float4*)&Bs[k][64 + tx * 4];
            float av[8] = {a0.x, a0.y, a0.z, a0.w, a1.x, a1.y, a1.z, a1.w};
            float bv[8] = {b0.x, b0.y, b0.z, b0.w, b1.x, b1.y, b1.z, b1.w};
            #pragma unroll
            for (int r = 0; r < 8; ++r)
                #pragma unroll
                for (int c = 0; c < 8; ++c)
                    acc[r][c] = fmaf(av[r], bv[c], acc[r][c]);
        }
        __syncthreads();
    }

    #pragma unroll
    for (int rg = 0; rg < 2; ++rg)
        #pragma unroll
        for (int q = 0; q < 4; ++q) {
            int i = bi + rg * 64 + ty * 4 + q;
            float sa = sqa[i];
            int r = rg * 4 + q;
            #pragma unroll
            for (int cg = 0; cg < 2; ++cg) {
                int j0 = bj + cg * 64 + tx * 4;
                float4 v;
                v.x = fmaxf(sa + sqb[j0 + 0] - acc[r][cg * 4 + 0], 0.f);
                v.y = fmaxf(sa + sqb[j0 + 1] - acc[r][cg * 4 + 1], 0.f);
                v.z = fmaxf(sa + sqb[j0 + 2] - acc[r][cg * 4 + 2], 0.f);
                v.w = fmaxf(sa + sqb[j0 + 3] - acc[r][cg * 4 + 3], 0.f);
                *(float4*)(C + (u64)i * Nn + j0) = v;
            }
        }
}

// ---------------- fused tile softmin (row + col LSE partials from one read) ----------
// Tile 128x128, 256 threads. Lane owns 4 cols x 16 rows in registers.
// sym=0 (xy): full grid; row partials -> pRM[bx], col partials -> pCM[by].
// sym=1 (xx/yy lower triangle): by<bx exits; col partials (for by>bx) go into the
//        SAME row-partial arrays at chunk=by (symmetry: col softmin == row softmin).
__global__ void __launch_bounds__(256) fused_softmin_kernel(
    const float* __restrict__ C,
    const float* __restrict__ potRow,   // indexed by columns (row-direction potential)
    const float* __restrict__ potCol,   // indexed by rows    (col-direction potential)
    const float* __restrict__ eps_ptr, float base, int init, int sym,
    float* __restrict__ pRM, float* __restrict__ pRS,
    float* __restrict__ pCM, float* __restrict__ pCS)
{
    const int bx = blockIdx.x, by = blockIdx.y;
    if (sym && by < bx) return;
    const bool doCol = (!sym) || (by > bx);
    const int bi = by * 128, bj = bx * 128;
    const int tid = threadIdx.x, lane = tid & 31, w = tid >> 5;
    const float inv = 1.0f / (*eps_ptr);

    __shared__ float gpot[128];       // base + potRow[bj+.]/eps
    __shared__ float fpot[128];       // base + potCol[bi+.]/eps
    __shared__ float cMsh[8][132], cSsh[8][132];

    if (tid < 128) gpot[tid] = init ? base : fmaf(potRow[bj + tid], inv, base);
    else { int t = tid - 128; fpot[t] = init ? base : fmaf(potCol[bi + t], inv, base); }
    __syncthreads();

    const int r0 = w * 16;
    float4 cw[16];
    #pragma unroll
    for (int r = 0; r < 16; ++r)
        cw[r] = *(const float4*)(C + (u64)(bi + r0 + r) * Nn + bj + 4 * lane);
    #pragma unroll
    for (int r = 0; r < 16; ++r) {
        cw[r].x *= inv; cw[r].y *= inv; cw[r].z *= inv; cw[r].w *= inv;
    }

    // ---- row phase: per-row warp LSE ----
    {
        float4 gp = *(const float4*)&gpot[4 * lane];
        #pragma unroll
        for (int r = 0; r < 16; ++r) {
            float v0 = gp.x - cw[r].x, v1 = gp.y - cw[r].y;
            float v2 = gp.z - cw[r].z, v3 = gp.w - cw[r].w;
            float m = fmaxf(fmaxf(v0, v1), fmaxf(v2, v3));
            #pragma unroll
            for (int o = 16; o; o >>= 1) m = fmaxf(m, __shfl_xor_sync(0xffffffffu, m, o));
            float s = __expf(v0 - m) + __expf(v1 - m) + __expf(v2 - m) + __expf(v3 - m);
            #pragma unroll
            for (int o = 16; o; o >>= 1) s += __shfl_xor_sync(0xffffffffu, s, o);
            if (lane == 0) {
                pRM[(u64)bx * Nn + bi + r0 + r] = m;
                pRS[(u64)bx * Nn + bi + r0 + r] = s;
            }
        }
    }

    // ---- col phase: per-lane LSE over its 16 rows for 4 cols, then 8-warp merge ----
    if (doCol) {
        #pragma unroll
        for (int e = 0; e < 4; ++e) {
            float vv[16];
            #pragma unroll
            for (int r = 0; r < 16; ++r) {
                float wv = (e == 0) ? cw[r].x : (e == 1) ? cw[r].y : (e == 2) ? cw[r].z : cw[r].w;
                vv[r] = fpot[r0 + r] - wv;
            }
            float m = vv[0];
            #pragma unroll
            for (int r = 1; r < 16; ++r) m = fmaxf(m, vv[r]);
            float s = 0.f;
            #pragma unroll
            for (int r = 0; r < 16; ++r) s += __expf(vv[r] - m);
            cMsh[w][4 * lane + e] = m;
            cSsh[w][4 * lane + e] = s;
        }
        __syncthreads();
        if (tid < 128) {
            float M = cMsh[0][tid];
            #pragma unroll
            for (int k = 1; k < 8; ++k) M = fmaxf(M, cMsh[k][tid]);
            float S = 0.f;
            #pragma unroll
            for (int k = 0; k < 8; ++k) S += cSsh[k][tid] * __expf(cMsh[k][tid] - M);
            float* dM = sym ? pRM : pCM;
            float* dS = sym ? pRS : pCS;
            dM[(u64)by * Nn + bj + tid] = M;
            dS[(u64)by * Nn + bj + tid] = S;
        }
    }
}

// ---------------- combine NCH per-tile LSE partials into final softmin ----------------
__global__ void __launch_bounds__(256) combine_kernel(
    const float* __restrict__ pM, const float* __restrict__ pS,
    const float* __restrict__ eps_ptr, float* __restrict__ out)
{
    int i = blockIdx.x * 256 + threadIdx.x;
    float eps = *eps_ptr;
    float M = -3.4e38f;
    #pragma unroll 8
    for (int c = 0; c < NCH; ++c) M = fmaxf(M, pM[(u64)c * Nn + i]);
    float S = 0.f;
    #pragma unroll 8
    for (int c = 0; c < NCH; ++c)
        S += pS[(u64)c * Nn + i] * __expf(pM[(u64)c * Nn + i] - M);
    out[i] = -eps * (logf(S) + M);
}

// ---------------- symmetrized dual update ----------------
__global__ void update_kernel(const float* __restrict__ tftaa, const float* __restrict__ tgtbb,
                              const float* __restrict__ tgt, const float* __restrict__ tft,
                              float* __restrict__ faa, float* __restrict__ gbb,
                              float* __restrict__ gab, float* __restrict__ fba)
{
    int i = blockIdx.x * blockDim.x + threadIdx.x;
    faa[i] = 0.5f * (faa[i] + tftaa[i]);
    gbb[i] = 0.5f * (gbb[i] + tgtbb[i]);
    gab[i] = 0.5f * (gab[i] + tgt[i]);
    fba[i] = 0.5f * (fba[i] + tft[i]);
}

// ---------------- final scalar ----------------
__global__ void final_kernel(const float* __restrict__ fbaf, const float* __restrict__ faaf,
                             const float* __restrict__ gabf, const float* __restrict__ gbbf,
                             float* __restrict__ out)
{
    __shared__ float red[32];
    int tid = threadIdx.x;
    int lane = tid & 31, wid = tid >> 5;
    float s = 0.f;
    for (int i = tid; i < Nn; i += 1024)
        s += (fbaf[i] - faaf[i]) + (gabf[i] - gbbf[i]);
    #pragma unroll
    for (int o = 16; o; o >>= 1) s += __shfl_xor_sync(0xffffffffu, s, o);
    if (lane == 0) red[wid] = s;
    __syncthreads();
    if (wid == 0) {
        float v = red[lane];
        #pragma unroll
        for (int o = 16; o; o >>= 1) v += __shfl_xor_sync(0xffffffffu, v, o);
        if (lane == 0) out[0] = v / (float)Nn;
    }
}

// ---------------- launch ----------------
extern "C" void kernel_launch(void* const* d_in, const int* in_sizes, int n_in,
                              void* d_out, int out_size)
{
    const float* X   = (const float*)d_in[0];
    const float* Y   = (const float*)d_in[1];
    const float* eps = (const float*)d_in[2];
    const int n_eps  = in_sizes[2];
    float* out = (float*)d_out;

    float *Cxy, *Cxx, *Cyy, *sqx, *sqy;
    float *faa, *gbb, *gab, *fba, *tft, *tgt, *tftaa, *tgtbb;
    float *pRM, *pRS, *pCM, *pCS;
    cudaGetSymbolAddress((void**)&Cxy, d_Cxy);
    cudaGetSymbolAddress((void**)&Cxx, d_Cxx);
    cudaGetSymbolAddress((void**)&Cyy, d_Cyy);
    cudaGetSymbolAddress((void**)&sqx, d_sqx);
    cudaGetSymbolAddress((void**)&sqy, d_sqy);
    cudaGetSymbolAddress((void**)&faa, d_faa);
    cudaGetSymbolAddress((void**)&gbb, d_gbb);
    cudaGetSymbolAddress((void**)&gab, d_gab);
    cudaGetSymbolAddress((void**)&fba, d_fba);
    cudaGetSymbolAddress((void**)&tft, d_tft);
    cudaGetSymbolAddress((void**)&tgt, d_tgt);
    cudaGetSymbolAddress((void**)&tftaa, d_tftaa);
    cudaGetSymbolAddress((void**)&tgtbb, d_tgtbb);
    cudaGetSymbolAddress((void**)&pRM, d_pRM);
    cudaGetSymbolAddress((void**)&pRS, d_pRS);
    cudaGetSymbolAddress((void**)&pCM, d_pCM);
    cudaGetSymbolAddress((void**)&pCS, d_pCS);

    const float LOGW = -logf((float)Nn);
    dim3 gg(NCH, NCH);

    sqnorm_kernel<<<1024, 256>>>(X, sqx);
    sqnorm_kernel<<<1024, 256>>>(Y, sqy);
    cost_gemm_kernel<<<gg, 256>>>(X, Y, sqx, sqy, Cxy, 0);
    cost_gemm_kernel<<<gg, 256>>>(X, X, sqx, sqx, Cxx, 1);
    cost_gemm_kernel<<<gg, 256>>>(Y, Y, sqy, sqy, Cyy, 1);

    // ---- init at eps0 ----
    fused_softmin_kernel<<<gg, 256>>>(Cxy, nullptr, nullptr, eps, LOGW, 1, 0,
                                      pRM, pRS, pCM, pCS);
    combine_kernel<<<Nn / 256, 256>>>(pRM, pRS, eps, fba);   // f_ba
    combine_kernel<<<Nn / 256, 256>>>(pCM, pCS, eps, gab);   // g_ab
    fused_softmin_kernel<<<gg, 256>>>(Cxx, nullptr, nullptr, eps, LOGW, 1, 1,
                                      pRM, pRS, pRM, pRS);
    combine_kernel<<<Nn / 256, 256>>>(pRM, pRS, eps, faa);   // f_aa
    fused_softmin_kernel<<<gg, 256>>>(Cyy, nullptr, nullptr, eps, LOGW, 1, 1,
                                      pRM, pRS, pRM, pRS);
    combine_kernel<<<Nn / 256, 256>>>(pRM, pRS, eps, gbb);   // g_bb

    // ---- annealed symmetric Sinkhorn scan ----
    for (int k = 0; k < n_eps; ++k) {
        const float* ek = eps + k;
        fused_softmin_kernel<<<gg, 256>>>(Cxy, gab, fba, ek, LOGW, 0, 0,
                                          pRM, pRS, pCM, pCS);
        combine_kernel<<<Nn / 256, 256>>>(pRM, pRS, ek, tft);
        combine_kernel<<<Nn / 256, 256>>>(pCM, pCS, ek, tgt);
        fused_softmin_kernel<<<gg, 256>>>(Cxx, faa, faa, ek, LOGW, 0, 1,
                                          pRM, pRS, pRM, pRS);
        combine_kernel<<<Nn / 256, 256>>>(pRM, pRS, ek, tftaa);
        fused_softmin_kernel<<<gg, 256>>>(Cyy, gbb, gbb, ek, LOGW, 0, 1,
                                          pRM, pRS, pRM, pRS);
        combine_kernel<<<Nn / 256, 256>>>(pRM, pRS, ek, tgtbb);
        update_kernel<<<Nn / 256, 256>>>(tftaa, tgtbb, tgt, tft, faa, gbb, gab, fba);
    }

    // ---- final extrapolation at eps = blur^p ----
    const float* el = eps + (n_eps - 1);
    fused_softmin_kernel<<<gg, 256>>>(Cxy, gab, fba, el, LOGW, 0, 0,
                                      pRM, pRS, pCM, pCS);
    combine_kernel<<<Nn / 256, 256>>>(pRM, pRS, el, tft);     // f_ba_f
    combine_kernel<<<Nn / 256, 256>>>(pCM, pCS, el, tgt);     // g_ab_f
    fused_softmin_kernel<<<gg, 256>>>(Cxx, faa, faa, el, LOGW, 0, 1,
                                      pRM, pRS, pRM, pRS);
    combine_kernel<<<Nn / 256, 256>>>(pRM, pRS, el, tftaa);   // f_aa_f
    fused_softmin_kernel<<<gg, 256>>>(Cyy, gbb, gbb, el, LOGW, 0, 1,
                                      pRM, pRS, pRM, pRS);
    combine_kernel<<<Nn / 256, 256>>>(pRM, pRS, el, tgtbb);   // g_bb_f

    final_kernel<<<1, 1024>>>(tft, tftaa, tgt, tgtbb, out);
}

// round 4
// speedup vs baseline: 1.3247x; 1.2289x over previous
#include <cuda_runtime.h>
#include <math.h>

typedef unsigned long long u64;

#define Nn 8192
#define Dd 64
#define NCH 64                 // 8192/128 chunks per dimension
#define NTRI (NCH * (NCH + 1) / 2)   // 2080 lower-triangle tiles
#define L2E 1.44269504088896f
#define LN2 0.69314718055995f

// ---------------- scratch (static device memory; no allocations) ----------------
__device__ float d_Cxy[(u64)Nn * Nn];
__device__ float d_Cxx[(u64)Nn * Nn];   // lower triangle (tile granularity) valid
__device__ float d_Cyy[(u64)Nn * Nn];
__device__ float d_sqx[Nn], d_sqy[Nn];
__device__ float d_faa[Nn], d_gbb[Nn], d_gab[Nn], d_fba[Nn];
__device__ float d_tft[Nn], d_tgt[Nn], d_tftaa[Nn], d_tgtbb[Nn];
__device__ float d_pRM[(u64)NCH * Nn], d_pRS[(u64)NCH * Nn];   // xy row partials
__device__ float d_pCM[(u64)NCH * Nn], d_pCS[(u64)NCH * Nn];   // xy col partials
__device__ float d_pXM[(u64)NCH * Nn], d_pXS[(u64)NCH * Nn];   // xx partials
__device__ float d_pYM[(u64)NCH * Nn], d_pYS[(u64)NCH * Nn];   // yy partials

__device__ __forceinline__ float ex2(float x) {
    float r; asm("ex2.approx.ftz.f32 %0, %1;" : "=f"(r) : "f"(x)); return r;
}
__device__ __forceinline__ float lg2(float x) {
    float r; asm("lg2.approx.f32 %0, %1;" : "=f"(r) : "f"(x)); return r;
}
__device__ __forceinline__ void tri_decode(int b, int& by, int& bx) {
    int r = (int)((sqrtf(8.0f * (float)b + 1.0f) - 1.0f) * 0.5f);
    while ((r + 1) * (r + 2) / 2 <= b) ++r;
    while (r * (r + 1) / 2 > b) --r;
    by = r; bx = b - r * (r + 1) / 2;
}

// ---------------- 0.5*||row||^2 ----------------
__global__ void sqnorm_kernel(const float* __restrict__ X, float* __restrict__ sq) {
    int gw   = (blockIdx.x * blockDim.x + threadIdx.x) >> 5;
    int lane = threadIdx.x & 31;
    if (gw >= Nn) return;
    const float* xr = X + (u64)gw * Dd;
    float a = xr[lane], b = xr[lane + 32];
    float s = a * a + b * b;
    #pragma unroll
    for (int o = 16; o; o >>= 1) s += __shfl_xor_sync(0xffffffffu, s, o);
    if (lane == 0) sq[gw] = 0.5f * s;
}

// ---------------- C[i][j] = max(0.5|a|^2 + 0.5|b|^2 - a.b, 0) ----------------
__global__ void __launch_bounds__(256, 2) cost_gemm_kernel(
    const float* __restrict__ A, const float* __restrict__ B,
    const float* __restrict__ sqa, const float* __restrict__ sqb,
    float* __restrict__ C, int sym)
{
    int bxi, byi;
    if (sym) tri_decode(blockIdx.x, byi, bxi);
    else { bxi = blockIdx.x; byi = blockIdx.y; }
    __shared__ float As[32][128];
    __shared__ float Bs[32][128];
    const int bi  = byi * 128;
    const int bj  = bxi * 128;
    const int tid = threadIdx.x;
    const int tx  = tid & 15, ty = tid >> 4;

    float acc[8][8];
    #pragma unroll
    for (int r = 0; r < 8; ++r)
        #pragma unroll
        for (int c = 0; c < 8; ++c) acc[r][c] = 0.f;

    for (int kc = 0; kc < Dd; kc += 32) {
        #pragma unroll
        for (int it = 0; it < 4; ++it) {
            int idx = tid + it * 256;
            int row = idx >> 3;
            int kq  = idx & 7;
            float4 a = *(const float4*)(A + (u64)(bi + row) * Dd + kc + kq * 4);
            float4 b = *(const float4*)(B + (u64)(bj + row) * Dd + kc + kq * 4);
            As[kq * 4 + 0][row] = a.x; As[kq * 4 + 1][row] = a.y;
            As[kq * 4 + 2][row] = a.z; As[kq * 4 + 3][row] = a.w;
            Bs[kq * 4 + 0][row] = b.x; Bs[kq * 4 + 1][row] = b.y;
            Bs[kq * 4 + 2][row] = b.z; Bs[kq * 4 + 3][row] = b.w;
        }
        __syncthreads();
        #pragma unroll
        for (int k = 0; k < 32; ++k) {
            float4 a0 = *(const float4*)&As[k][ty * 4];
            float4 a1 = *(const float4*)&As[k][64 + ty * 4];
            float4 b0 = *(const float4*)&Bs[k][tx * 4];
            float4 b1 = *(const float4*)&Bs[k][64 + tx * 4];
            float av[8] = {a0.x, a0.y, a0.z, a0.w, a1.x, a1.y, a1.z, a1.w};
            float bv[8] = {b0.x, b0.y, b0.z, b0.w, b1.x, b1.y, b1.z, b1.w};
            #pragma unroll
            for (int r = 0; r < 8; ++r)
                #pragma unroll
                for (int c = 0; c < 8; ++c)
                    acc[r][c] = fmaf(av[r], bv[c], acc[r][c]);
        }
        __syncthreads();
    }

    #pragma unroll
    for (int rg = 0; rg < 2; ++rg)
        #pragma unroll
        for (int q = 0; q < 4; ++q) {
            int i = bi + rg * 64 + ty * 4 + q;
            float sa = sqa[i];
            int r = rg * 4 + q;
            #pragma unroll
            for (int cg = 0; cg < 2; ++cg) {
                int j0 = bj + cg * 64 + tx * 4;
                float4 v;
                v.x = fmaxf(sa + sqb[j0 + 0] - acc[r][cg * 4 + 0], 0.f);
                v.y = fmaxf(sa + sqb[j0 + 1] - acc[r][cg * 4 + 1], 0.f);
                v.z = fmaxf(sa + sqb[j0 + 2] - acc[r][cg * 4 + 2], 0.f);
                v.w = fmaxf(sa + sqb[j0 + 3] - acc[r][cg * 4 + 3], 0.f);
                *(float4*)(C + (u64)i * Nn + j0) = v;
            }
        }
}

// ---------------- fused tile softmin (row + col LSE partials, log2 domain) ----------
// Tile 128x128, 256 threads, lane owns 4 cols x 16 rows in registers.
// sym=0: grid (64,64); row partials -> pRM[bx], col partials -> pCM[by].
// sym=1: 1-D triangular grid; col partials (by>bx) go into pRM at chunk by.
__global__ void __launch_bounds__(256, 2) fused_softmin_kernel(
    const float* __restrict__ C,
    const float* __restrict__ potRow, const float* __restrict__ potCol,
    const float* __restrict__ eps_ptr, float base, int init, int sym,
    float* __restrict__ pRM, float* __restrict__ pRS,
    float* __restrict__ pCM, float* __restrict__ pCS)
{
    int bx, by;
    if (sym) tri_decode(blockIdx.x, by, bx);
    else { bx = blockIdx.x; by = blockIdx.y; }
    const bool doCol = (!sym) || (by > bx);
    const int bi = by * 128, bj = bx * 128;
    const int tid = threadIdx.x, lane = tid & 31, w = tid >> 5;
    const float s2 = L2E / (*eps_ptr);     // log2 scaling
    const float b2 = base * L2E;

    __shared__ float gpot[128];       // b2 + potRow[bj+.]*s2  (row direction)
    __shared__ float fpot[128];       // b2 + potCol[bi+.]*s2  (col direction)
    __shared__ float cMsh[8][132], cSsh[8][132];

    if (tid < 128) gpot[tid] = init ? b2 : fmaf(potRow[bj + tid], s2, b2);
    else { int t = tid - 128; fpot[t] = init ? b2 : fmaf(potCol[bi + t], s2, b2); }
    __syncthreads();

    const int r0 = w * 16;
    float4 cw[16];
    #pragma unroll
    for (int r = 0; r < 16; ++r)
        cw[r] = __ldcs((const float4*)(C + (u64)(bi + r0 + r) * Nn + bj + 4 * lane));
    #pragma unroll
    for (int r = 0; r < 16; ++r) {
        cw[r].x *= s2; cw[r].y *= s2; cw[r].z *= s2; cw[r].w *= s2;
    }

    // ---- row phase ----
    {
        float4 gp = *(const float4*)&gpot[4 * lane];
        #pragma unroll
        for (int r = 0; r < 16; ++r) {
            float v0 = gp.x - cw[r].x, v1 = gp.y - cw[r].y;
            float v2 = gp.z - cw[r].z, v3 = gp.w - cw[r].w;
            float m = fmaxf(fmaxf(v0, v1), fmaxf(v2, v3));
            #pragma unroll
            for (int o = 16; o; o >>= 1) m = fmaxf(m, __shfl_xor_sync(0xffffffffu, m, o));
            float s = ex2(v0 - m) + ex2(v1 - m) + ex2(v2 - m) + ex2(v3 - m);
            #pragma unroll
            for (int o = 16; o; o >>= 1) s += __shfl_xor_sync(0xffffffffu, s, o);
            if (lane == 0) {
                pRM[(u64)bx * Nn + bi + r0 + r] = m;
                pRS[(u64)bx * Nn + bi + r0 + r] = s;
            }
        }
    }

    // ---- col phase ----
    if (doCol) {
        #pragma unroll
        for (int e = 0; e < 4; ++e) {
            float vv[16];
            #pragma unroll
            for (int r = 0; r < 16; ++r) {
                float wv = (e == 0) ? cw[r].x : (e == 1) ? cw[r].y : (e == 2) ? cw[r].z : cw[r].w;
                vv[r] = fpot[r0 + r] - wv;
            }
            float m = vv[0];
            #pragma unroll
            for (int r = 1; r < 16; ++r) m = fmaxf(m, vv[r]);
            float s = 0.f;
            #pragma unroll
            for (int r = 0; r < 16; ++r) s += ex2(vv[r] - m);
            cMsh[w][4 * lane + e] = m;
            cSsh[w][4 * lane + e] = s;
        }
        __syncthreads();
        if (tid < 128) {
            float M = cMsh[0][tid];
            #pragma unroll
            for (int k = 1; k < 8; ++k) M = fmaxf(M, cMsh[k][tid]);
            float S = 0.f;
            #pragma unroll
            for (int k = 0; k < 8; ++k) S += cSsh[k][tid] * ex2(cMsh[k][tid] - M);
            float* dM = sym ? pRM : pCM;
            float* dS = sym ? pRS : pCS;
            dM[(u64)by * Nn + bj + tid] = M;
            dS[(u64)by * Nn + bj + tid] = S;
        }
    }
}

// ---------------- fused combine of all four partial sets + dual update --------------
// mode 0: init  -> write faa/gbb/gab/fba directly
// mode 1: iter  -> symmetrized in-place update of faa/gbb/gab/fba
// mode 2: final -> write tft/tgt/tftaa/tgtbb
__global__ void __launch_bounds__(256) combine_update_kernel(
    const float* __restrict__ pRM, const float* __restrict__ pRS,
    const float* __restrict__ pCM, const float* __restrict__ pCS,
    const float* __restrict__ pXM, const float* __restrict__ pXS,
    const float* __restrict__ pYM, const float* __restrict__ pYS,
    const float* __restrict__ eps_ptr, int mode,
    float* __restrict__ faa, float* __restrict__ gbb,
    float* __restrict__ gab, float* __restrict__ fba,
    float* __restrict__ tft, float* __restrict__ tgt,
    float* __restrict__ tftaa, float* __restrict__ tgtbb)
{
    const int i = blockIdx.x * 256 + threadIdx.x;
    const float eps = *eps_ptr;
    const float sc = -eps * LN2;

    float M, S, ft, gt, ftaa, gtbb;

    M = -3.4e38f;
    #pragma unroll 8
    for (int c = 0; c < NCH; ++c) M = fmaxf(M, pRM[(u64)c * Nn + i]);
    S = 0.f;
    #pragma unroll 8
    for (int c = 0; c < NCH; ++c) S += pRS[(u64)c * Nn + i] * ex2(pRM[(u64)c * Nn + i] - M);
    ft = sc * (lg2(S) + M);

    M = -3.4e38f;
    #pragma unroll 8
    for (int c = 0; c < NCH; ++c) M = fmaxf(M, pCM[(u64)c * Nn + i]);
    S = 0.f;
    #pragma unroll 8
    for (int c = 0; c < NCH; ++c) S += pCS[(u64)c * Nn + i] * ex2(pCM[(u64)c * Nn + i] - M);
    gt = sc * (lg2(S) + M);

    M = -3.4e38f;
    #pragma unroll 8
    for (int c = 0; c < NCH; ++c) M = fmaxf(M, pXM[(u64)c * Nn + i]);
    S = 0.f;
    #pragma unroll 8
    for (int c = 0; c < NCH; ++c) S += pXS[(u64)c * Nn + i] * ex2(pXM[(u64)c * Nn + i] - M);
    ftaa = sc * (lg2(S) + M);

    M = -3.4e38f;
    #pragma unroll 8
    for (int c = 0; c < NCH; ++c) M = fmaxf(M, pYM[(u64)c * Nn + i]);
    S = 0.f;
    #pragma unroll 8
    for (int c = 0; c < NCH; ++c) S += pYS[(u64)c * Nn + i] * ex2(pYM[(u64)c * Nn + i] - M);
    gtbb = sc * (lg2(S) + M);

    if (mode == 0) {
        fba[i] = ft; gab[i] = gt; faa[i] = ftaa; gbb[i] = gtbb;
    } else if (mode == 1) {
        faa[i] = 0.5f * (faa[i] + ftaa);
        gbb[i] = 0.5f * (gbb[i] + gtbb);
        gab[i] = 0.5f * (gab[i] + gt);
        fba[i] = 0.5f * (fba[i] + ft);
    } else {
        tft[i] = ft; tgt[i] = gt; tftaa[i] = ftaa; tgtbb[i] = gtbb;
    }
}

// ---------------- final scalar ----------------
__global__ void final_kernel(const float* __restrict__ fbaf, const float* __restrict__ faaf,
                             const float* __restrict__ gabf, const float* __restrict__ gbbf,
                             float* __restrict__ out)
{
    __shared__ float red[32];
    int tid = threadIdx.x;
    int lane = tid & 31, wid = tid >> 5;
    float s = 0.f;
    for (int i = tid; i < Nn; i += 1024)
        s += (fbaf[i] - faaf[i]) + (gabf[i] - gbbf[i]);
    #pragma unroll
    for (int o = 16; o; o >>= 1) s += __shfl_xor_sync(0xffffffffu, s, o);
    if (lane == 0) red[wid] = s;
    __syncthreads();
    if (wid == 0) {
        float v = red[lane];
        #pragma unroll
        for (int o = 16; o; o >>= 1) v += __shfl_xor_sync(0xffffffffu, v, o);
        if (lane == 0) out[0] = v / (float)Nn;
    }
}

// ---------------- launch ----------------
extern "C" void kernel_launch(void* const* d_in, const int* in_sizes, int n_in,
                              void* d_out, int out_size)
{
    const float* X   = (const float*)d_in[0];
    const float* Y   = (const float*)d_in[1];
    const float* eps = (const float*)d_in[2];
    const int n_eps  = in_sizes[2];
    float* out = (float*)d_out;

    float *Cxy, *Cxx, *Cyy, *sqx, *sqy;
    float *faa, *gbb, *gab, *fba, *tft, *tgt, *tftaa, *tgtbb;
    float *pRM, *pRS, *pCM, *pCS, *pXM, *pXS, *pYM, *pYS;
    cudaGetSymbolAddress((void**)&Cxy, d_Cxy);
    cudaGetSymbolAddress((void**)&Cxx, d_Cxx);
    cudaGetSymbolAddress((void**)&Cyy, d_Cyy);
    cudaGetSymbolAddress((void**)&sqx, d_sqx);
    cudaGetSymbolAddress((void**)&sqy, d_sqy);
    cudaGetSymbolAddress((void**)&faa, d_faa);
    cudaGetSymbolAddress((void**)&gbb, d_gbb);
    cudaGetSymbolAddress((void**)&gab, d_gab);
    cudaGetSymbolAddress((void**)&fba, d_fba);
    cudaGetSymbolAddress((void**)&tft, d_tft);
    cudaGetSymbolAddress((void**)&tgt, d_tgt);
    cudaGetSymbolAddress((void**)&tftaa, d_tftaa);
    cudaGetSymbolAddress((void**)&tgtbb, d_tgtbb);
    cudaGetSymbolAddress((void**)&pRM, d_pRM);
    cudaGetSymbolAddress((void**)&pRS, d_pRS);
    cudaGetSymbolAddress((void**)&pCM, d_pCM);
    cudaGetSymbolAddress((void**)&pCS, d_pCS);
    cudaGetSymbolAddress((void**)&pXM, d_pXM);
    cudaGetSymbolAddress((void**)&pXS, d_pXS);
    cudaGetSymbolAddress((void**)&pYM, d_pYM);
    cudaGetSymbolAddress((void**)&pYS, d_pYS);

    const float LOGW = -logf((float)Nn);
    dim3 gg(NCH, NCH);

    sqnorm_kernel<<<1024, 256>>>(X, sqx);
    sqnorm_kernel<<<1024, 256>>>(Y, sqy);
    cost_gemm_kernel<<<gg, 256>>>(X, Y, sqx, sqy, Cxy, 0);
    cost_gemm_kernel<<<NTRI, 256>>>(X, X, sqx, sqx, Cxx, 1);
    cost_gemm_kernel<<<NTRI, 256>>>(Y, Y, sqy, sqy, Cyy, 1);

    // one "round" = 3 fused softmins + 1 combine
    for (int k = -1; k <= n_eps; ++k) {
        const float* ek = (k < 0) ? eps : (k < n_eps ? eps + k : eps + (n_eps - 1));
        int mode = (k < 0) ? 0 : (k < n_eps ? 1 : 2);
        int init = (k < 0) ? 1 : 0;
        fused_softmin_kernel<<<gg, 256>>>(Cxy, gab, fba, ek, LOGW, init, 0,
                                          pRM, pRS, pCM, pCS);
        fused_softmin_kernel<<<NTRI, 256>>>(Cxx, faa, faa, ek, LOGW, init, 1,
                                            pXM, pXS, pXM, pXS);
        fused_softmin_kernel<<<NTRI, 256>>>(Cyy, gbb, gbb, ek, LOGW, init, 1,
                                            pYM, pYS, pYM, pYS);
        combine_update_kernel<<<Nn / 256, 256>>>(pRM, pRS, pCM, pCS, pXM, pXS, pYM, pYS,
                                                 ek, mode,
                                                 faa, gbb, gab, fba,
                                                 tft, tgt, tftaa, tgtbb);
    }

    final_kernel<<<1, 1024>>>(tft, tftaa, tgt, tgtbb, out);
}

// round 6
// speedup vs baseline: 1.7275x; 1.3041x over previous
#include <cuda_runtime.h>
#include <math.h>
#include <stdint.h>

typedef unsigned long long u64;
typedef unsigned int u32;
typedef unsigned short u16;

#define Nn 8192
#define NCH 64
#define NTRI (NCH * (NCH + 1) / 2)
#define L2E 1.44269504088896f
#define LN2 0.69314718055995f

// ---------------- static scratch ----------------
__device__ u16 d_Cxy[(u64)Nn * Nn];
__device__ u16 d_Cxx[(u64)Nn * Nn];   // lower-triangle tiles valid
__device__ u16 d_Cyy[(u64)Nn * Nn];
__device__ float d_sqx[Nn], d_sqy[Nn];
__device__ float d_scales[6];          // scale xy,xx,yy ; inv xy,xx,yy
__device__ float d_faa[Nn], d_gbb[Nn], d_gab[Nn], d_fba[Nn];
__device__ float d_tft[Nn], d_tgt[Nn], d_tftaa[Nn], d_tgtbb[Nn];
__device__ float d_pRM[(u64)NCH * Nn], d_pRS[(u64)NCH * Nn];
__device__ float d_pCM[(u64)NCH * Nn], d_pCS[(u64)NCH * Nn];
__device__ float d_pXM[(u64)NCH * Nn], d_pXS[(u64)NCH * Nn];
__device__ float d_pYM[(u64)NCH * Nn], d_pYS[(u64)NCH * Nn];

__device__ __forceinline__ float ex2(float x) {
    float r; asm("ex2.approx.ftz.f32 %0, %1;" : "=f"(r) : "f"(x)); return r;
}
__device__ __forceinline__ float lg2(float x) {
    float r; asm("lg2.approx.f32 %0, %1;" : "=f"(r) : "f"(x)); return r;
}
__device__ __forceinline__ void tri_decode(int b, int& by, int& bx) {
    int r = (int)((sqrtf(8.0f * (float)b + 1.0f) - 1.0f) * 0.5f);
    while ((r + 1) * (r + 2) / 2 <= b) ++r;
    while (r * (r + 1) / 2 > b) --r;
    by = r; bx = b - r * (r + 1) / 2;
}
// assemble float(2^23 + q) from a packed u32 holding two u16s
__device__ __forceinline__ float q2f_lo(u32 a) {
    return __uint_as_float(__byte_perm(a, 0x4B000000u, 0x7410));
}
__device__ __forceinline__ float q2f_hi(u32 a) {
    return __uint_as_float(__byte_perm(a, 0x4B000000u, 0x7432));
}

// ---------------- 0.5*||row||^2 ----------------
__global__ void sqnorm_kernel(const float* __restrict__ X, float* __restrict__ sq) {
    int gw   = (blockIdx.x * blockDim.x + threadIdx.x) >> 5;
    int lane = threadIdx.x & 31;
    if (gw >= Nn) return;
    const float* xr = X + (u64)gw * 64;
    float a = xr[lane], b = xr[lane + 32];
    float s = a * a + b * b;
    #pragma unroll
    for (int o = 16; o; o >>= 1) s += __shfl_xor_sync(0xffffffffu, s, o);
    if (lane == 0) sq[gw] = 0.5f * s;
}

// ---------------- global quantization scales from sqnorm maxima ----------------
__global__ void scale_kernel(const float* __restrict__ sqx, const float* __restrict__ sqy,
                             float* __restrict__ scales) {
    __shared__ float red[16];
    int tid = threadIdx.x, lane = tid & 31, w = tid >> 5;
    float mx = 0.f, my = 0.f;
    for (int i = tid; i < Nn; i += 256) {
        mx = fmaxf(mx, sqx[i]);
        my = fmaxf(my, sqy[i]);
    }
    #pragma unroll
    for (int o = 16; o; o >>= 1) {
        mx = fmaxf(mx, __shfl_xor_sync(0xffffffffu, mx, o));
        my = fmaxf(my, __shfl_xor_sync(0xffffffffu, my, o));
    }
    if (lane == 0) { red[w] = mx; red[w + 8] = my; }
    __syncthreads();
    if (tid == 0) {
        float MX = red[0], MY = red[8];
        #pragma unroll
        for (int i = 1; i < 8; ++i) { MX = fmaxf(MX, red[i]); MY = fmaxf(MY, red[8 + i]); }
        float cxy = MX + MY + 2.0f * sqrtf(MX * MY);
        float cxx = 4.0f * MX;
        float cyy = 4.0f * MY;
        scales[0] = cxy / 65500.0f; scales[3] = 65500.0f / cxy;
        scales[1] = cxx / 65500.0f; scales[4] = 65500.0f / cxx;
        scales[2] = cyy / 65500.0f; scales[5] = 65500.0f / cyy;
    }
}

// ---------------- cost GEMM -> quantized u16 ----------------
__global__ void __launch_bounds__(256, 2) cost_gemm_kernel(
    const float* __restrict__ A, const float* __restrict__ B,
    const float* __restrict__ sqa, const float* __restrict__ sqb,
    const float* __restrict__ inv_ptr, u16* __restrict__ Cq, int sym)
{
    int bxi, byi;
    if (sym) tri_decode(blockIdx.x, byi, bxi);
    else { bxi = blockIdx.x; byi = blockIdx.y; }
    __shared__ float As[32][128];
    __shared__ float Bs[32][128];
    const int bi  = byi * 128;
    const int bj  = bxi * 128;
    const int tid = threadIdx.x;
    const int tx  = tid & 15, ty = tid >> 4;
    const float inv = *inv_ptr;

    float acc[8][8];
    #pragma unroll
    for (int r = 0; r < 8; ++r)
        #pragma unroll
        for (int c = 0; c < 8; ++c) acc[r][c] = 0.f;

    for (int kc = 0; kc < 64; kc += 32) {
        #pragma unroll
        for (int it = 0; it < 4; ++it) {
            int idx = tid + it * 256;
            int row = idx >> 3;
            int kq  = idx & 7;
            float4 a = *(const float4*)(A + (u64)(bi + row) * 64 + kc + kq * 4);
            float4 b = *(const float4*)(B + (u64)(bj + row) * 64 + kc + kq * 4);
            As[kq * 4 + 0][row] = a.x; As[kq * 4 + 1][row] = a.y;
            As[kq * 4 + 2][row] = a.z; As[kq * 4 + 3][row] = a.w;
            Bs[kq * 4 + 0][row] = b.x; Bs[kq * 4 + 1][row] = b.y;
            Bs[kq * 4 + 2][row] = b.z; Bs[kq * 4 + 3][row] = b.w;
        }
        __syncthreads();
        #pragma unroll
        for (int k = 0; k < 32; ++k) {
            float4 a0 = *(const float4*)&As[k][ty * 4];
            float4 a1 = *(const float4*)&As[k][64 + ty * 4];
            float4 b0 = *(const float4*)&Bs[k][tx * 4];
            float4 b1 = *(const float4*)&Bs[k][64 + tx * 4];
            float av[8] = {a0.x, a0.y, a0.z, a0.w, a1.x, a1.y, a1.z, a1.w};
            float bv[8] = {b0.x, b0.y, b0.z, b0.w, b1.x, b1.y, b1.z, b1.w};
            #pragma unroll
            for (int r = 0; r < 8; ++r)
                #pragma unroll
                for (int c = 0; c < 8; ++c)
                    acc[r][c] = fmaf(av[r], bv[c], acc[r][c]);
        }
        __syncthreads();
    }

    #pragma unroll
    for (int rg = 0; rg < 2; ++rg)
        #pragma unroll
        for (int q = 0; q < 4; ++q) {
            int i = bi + rg * 64 + ty * 4 + q;
            float sa = sqa[i];
            int r = rg * 4 + q;
            #pragma unroll
            for (int cg = 0; cg < 2; ++cg) {
                int j0 = bj + cg * 64 + tx * 4;
                float v0 = fmaxf(sa + sqb[j0 + 0] - acc[r][cg * 4 + 0], 0.f);
                float v1 = fmaxf(sa + sqb[j0 + 1] - acc[r][cg * 4 + 1], 0.f);
                float v2 = fmaxf(sa + sqb[j0 + 2] - acc[r][cg * 4 + 2], 0.f);
                float v3 = fmaxf(sa + sqb[j0 + 3] - acc[r][cg * 4 + 3], 0.f);
                u32 b0 = __float_as_uint(fmaf(v0, inv, 8388608.0f));
                u32 b1 = __float_as_uint(fmaf(v1, inv, 8388608.0f));
                u32 b2 = __float_as_uint(fmaf(v2, inv, 8388608.0f));
                u32 b3 = __float_as_uint(fmaf(v3, inv, 8388608.0f));
                uint2 o;
                o.x = __byte_perm(b0, b1, 0x5410);
                o.y = __byte_perm(b2, b3, 0x5410);
                *(uint2*)(Cq + (u64)i * Nn + j0) = o;
            }
        }
}

// ---------------- tile softmin over quantized matrix (row + col partials) ----------
// 128x128 tile, 256 threads. Thread t: c16 = t&15 (8 contiguous cols), rp = t>>4,
// rows rp + 16*p (p=0..7). Thread-local LSE partials merged through padded smem.
__global__ void __launch_bounds__(256, 2) tile_softmin_kernel(
    const uint4* __restrict__ Q,
    const float* __restrict__ potRow,   // column-indexed potential (row phase)
    const float* __restrict__ potCol,   // row-indexed potential (col phase)
    const float* __restrict__ scale_ptr,
    const float* __restrict__ eps_ptr, float base_log, int init, int sym,
    float* __restrict__ pRM, float* __restrict__ pRS,
    float* __restrict__ pCM, float* __restrict__ pCS)
{
    int bx, by;
    if (sym) tri_decode(blockIdx.x, by, bx);
    else { bx = blockIdx.x; by = blockIdx.y; }
    const bool doCol = (!sym) || (by > bx);
    const int tid = threadIdx.x;
    const int c16 = tid & 15, rp = tid >> 4;

    const float s2   = L2E / (*eps_ptr);
    const float b2   = base_log * L2E;
    const float scs2 = (*scale_ptr) * s2;
    const float off  = b2 + 8388608.0f * scs2;   // folds the 2^23 bias out

    __shared__ float gp[128];
    __shared__ float fp[128];
    __shared__ float2 part[128 * 17];            // 17.4KB, reused row->col

    if (tid < 128) {
        float pv = init ? 0.f : potRow[bx * 128 + tid];
        gp[tid] = fmaf(pv, s2, off);
    } else {
        int t = tid - 128;
        float pv = init ? 0.f : potCol[by * 128 + t];
        fp[t] = fmaf(pv, s2, off);
    }
    __syncthreads();

    // my 8 column constants + 8 row constants
    float4 gA = *(const float4*)&gp[c16 * 8];
    float4 gB = *(const float4*)&gp[c16 * 8 + 4];
    float fpv[8];
    #pragma unroll
    for (int p = 0; p < 8; ++p) fpv[p] = fp[rp + 16 * p];

    // load 8 rows x 8 cols of u16 (uint4 = 8 values)
    uint4 qv[8];
    #pragma unroll
    for (int p = 0; p < 8; ++p)
        qv[p] = __ldcs(&Q[(u64)(by * 128 + rp + 16 * p) * 1024 + bx * 16 + c16]);

    const float nscs2 = -scs2;

    // ---- row phase: per-pass 8-wide LSE, write partial (m,s) per (row, c16) ----
    #pragma unroll
    for (int p = 0; p < 8; ++p) {
        float v0 = fmaf(q2f_lo(qv[p].x), nscs2, gA.x);
        float v1 = fmaf(q2f_hi(qv[p].x), nscs2, gA.y);
        float v2 = fmaf(q2f_lo(qv[p].y), nscs2, gA.z);
        float v3 = fmaf(q2f_hi(qv[p].y), nscs2, gA.w);
        float v4 = fmaf(q2f_lo(qv[p].z), nscs2, gB.x);
        float v5 = fmaf(q2f_hi(qv[p].z), nscs2, gB.y);
        float v6 = fmaf(q2f_lo(qv[p].w), nscs2, gB.z);
        float v7 = fmaf(q2f_hi(qv[p].w), nscs2, gB.w);
        float m = fmaxf(fmaxf(fmaxf(v0, v1), fmaxf(v2, v3)),
                        fmaxf(fmaxf(v4, v5), fmaxf(v6, v7)));
        float s = ((ex2(v0 - m) + ex2(v1 - m)) + (ex2(v2 - m) + ex2(v3 - m)))
                + ((ex2(v4 - m) + ex2(v5 - m)) + (ex2(v6 - m) + ex2(v7 - m)));
        part[(rp + 16 * p) * 17 + c16] = make_float2(m, s);
    }
    __syncthreads();

    // ---- row merge: thread tid<128 merges 16 partials of row tid ----
    if (tid < 128) {
        float M = -3.4e38f;
        float2 pr[16];
        #pragma unroll
        for (int k = 0; k < 16; ++k) { pr[k] = part[tid * 17 + k]; M = fmaxf(M, pr[k].x); }
        float S = 0.f;
        #pragma unroll
        for (int k = 0; k < 16; ++k) S += pr[k].y * ex2(pr[k].x - M);
        u64 oidx = (u64)bx * Nn + by * 128 + tid;
        pRM[oidx] = M;
        pRS[oidx] = S;
    }

    // ---- col phase ----
    if (doCol) {
        __syncthreads();   // row merge done reading part
        #pragma unroll
        for (int e = 0; e < 8; ++e) {
            float v[8];
            #pragma unroll
            for (int p = 0; p < 8; ++p) {
                u32 a = (e < 2) ? qv[p].x : (e < 4) ? qv[p].y : (e < 6) ? qv[p].z : qv[p].w;
                float fq = (e & 1) ? q2f_hi(a) : q2f_lo(a);
                v[p] = fmaf(fq, nscs2, fpv[p]);
            }
            float m = fmaxf(fmaxf(fmaxf(v[0], v[1]), fmaxf(v[2], v[3])),
                            fmaxf(fmaxf(v[4], v[5]), fmaxf(v[6], v[7])));
            float s = ((ex2(v[0] - m) + ex2(v[1] - m)) + (ex2(v[2] - m) + ex2(v[3] - m)))
                    + ((ex2(v[4] - m) + ex2(v[5] - m)) + (ex2(v[6] - m) + ex2(v[7] - m)));
            // layout [rp][e][c16] with pad-17
            part[(rp * 8 + e) * 17 + c16] = make_float2(m, s);
        }
        __syncthreads();
        if (tid < 128) {
            int e = tid & 7, cc = tid >> 3;    // col = cc*8+e ... careful: col index = c16*8+e
            // col global = (tid>>3)*8 + (tid&7)? We stored per (rp, e, c16): col = c16*8+e.
            // Thread handles col = tid: c16 = tid>>3, e = tid&7.
            float M = -3.4e38f;
            float2 pc[16];
            #pragma unroll
            for (int k = 0; k < 16; ++k) {
                pc[k] = part[(k * 8 + e) * 17 + cc];
                M = fmaxf(M, pc[k].x);
            }
            float S = 0.f;
            #pragma unroll
            for (int k = 0; k < 16; ++k) S += pc[k].y * ex2(pc[k].x - M);
            int col = cc * 8 + e;
            u64 oidx = (u64)by * Nn + bx * 128 + col;
            pCM[oidx] = M;
            pCS[oidx] = S;
        }
    }
}

// ---------------- combine all four partial sets + dual update ----------------
__global__ void __launch_bounds__(256) combine_update_kernel(
    const float* __restrict__ pRM, const float* __restrict__ pRS,
    const float* __restrict__ pCM, const float* __restrict__ pCS,
    const float* __restrict__ pXM, const float* __restrict__ pXS,
    const float* __restrict__ pYM, const float* __restrict__ pYS,
    const float* __restrict__ eps_ptr, int mode,
    float* __restrict__ faa, float* __restrict__ gbb,
    float* __restrict__ gab, float* __restrict__ fba,
    float* __restrict__ tft, float* __restrict__ tgt,
    float* __restrict__ tftaa, float* __restrict__ tgtbb)
{
    const int i = blockIdx.x * 256 + threadIdx.x;
    const float eps = *eps_ptr;
    const float sc = -eps * LN2;
    float M, S, ft, gt, ftaa, gtbb;

    M = -3.4e38f;
    #pragma unroll 8
    for (int c = 0; c < NCH; ++c) M = fmaxf(M, pRM[(u64)c * Nn + i]);
    S = 0.f;
    #pragma unroll 8
    for (int c = 0; c < NCH; ++c) S += pRS[(u64)c * Nn + i] * ex2(pRM[(u64)c * Nn + i] - M);
    ft = sc * (lg2(S) + M);

    M = -3.4e38f;
    #pragma unroll 8
    for (int c = 0; c < NCH; ++c) M = fmaxf(M, pCM[(u64)c * Nn + i]);
    S = 0.f;
    #pragma unroll 8
    for (int c = 0; c < NCH; ++c) S += pCS[(u64)c * Nn + i] * ex2(pCM[(u64)c * Nn + i] - M);
    gt = sc * (lg2(S) + M);

    M = -3.4e38f;
    #pragma unroll 8
    for (int c = 0; c < NCH; ++c) M = fmaxf(M, pXM[(u64)c * Nn + i]);
    S = 0.f;
    #pragma unroll 8
    for (int c = 0; c < NCH; ++c) S += pXS[(u64)c * Nn + i] * ex2(pXM[(u64)c * Nn + i] - M);
    ftaa = sc * (lg2(S) + M);

    M = -3.4e38f;
    #pragma unroll 8
    for (int c = 0; c < NCH; ++c) M = fmaxf(M, pYM[(u64)c * Nn + i]);
    S = 0.f;
    #pragma unroll 8
    for (int c = 0; c < NCH; ++c) S += pYS[(u64)c * Nn + i] * ex2(pYM[(u64)c * Nn + i] - M);
    gtbb = sc * (lg2(S) + M);

    if (mode == 0) {
        fba[i] = ft; gab[i] = gt; faa[i] = ftaa; gbb[i] = gtbb;
    } else if (mode == 1) {
        faa[i] = 0.5f * (faa[i] + ftaa);
        gbb[i] = 0.5f * (gbb[i] + gtbb);
        gab[i] = 0.5f * (gab[i] + gt);
        fba[i] = 0.5f * (fba[i] + ft);
    } else {
        tft[i] = ft; tgt[i] = gt; tftaa[i] = ftaa; tgtbb[i] = gtbb;
    }
}

// ---------------- final scalar ----------------
__global__ void final_kernel(const float* __restrict__ fbaf, const float* __restrict__ faaf,
                             const float* __restrict__ gabf, const float* __restrict__ gbbf,
                             float* __restrict__ out)
{
    __shared__ float red[32];
    int tid = threadIdx.x;
    int lane = tid & 31, wid = tid >> 5;
    float s = 0.f;
    for (int i = tid; i < Nn; i += 1024)
        s += (fbaf[i] - faaf[i]) + (gabf[i] - gbbf[i]);
    #pragma unroll
    for (int o = 16; o; o >>= 1) s += __shfl_xor_sync(0xffffffffu, s, o);
    if (lane == 0) red[wid] = s;
    __syncthreads();
    if (wid == 0) {
        float v = red[lane];
        #pragma unroll
        for (int o = 16; o; o >>= 1) v += __shfl_xor_sync(0xffffffffu, v, o);
        if (lane == 0) out[0] = v / (float)Nn;
    }
}

// ---------------- launch ----------------
extern "C" void kernel_launch(void* const* d_in, const int* in_sizes, int n_in,
                              void* d_out, int out_size)
{
    const float* X   = (const float*)d_in[0];
    const float* Y   = (const float*)d_in[1];
    const float* eps = (const float*)d_in[2];
    const int n_eps  = in_sizes[2];
    float* out = (float*)d_out;

    u16 *Cxy, *Cxx, *Cyy;
    float *sqx, *sqy, *scales;
    float *faa, *gbb, *gab, *fba, *tft, *tgt, *tftaa, *tgtbb;
    float *pRM, *pRS, *pCM, *pCS, *pXM, *pXS, *pYM, *pYS;
    cudaGetSymbolAddress((void**)&Cxy, d_Cxy);
    cudaGetSymbolAddress((void**)&Cxx, d_Cxx);
    cudaGetSymbolAddress((void**)&Cyy, d_Cyy);
    cudaGetSymbolAddress((void**)&sqx, d_sqx);
    cudaGetSymbolAddress((void**)&sqy, d_sqy);
    cudaGetSymbolAddress((void**)&scales, d_scales);
    cudaGetSymbolAddress((void**)&faa, d_faa);
    cudaGetSymbolAddress((void**)&gbb, d_gbb);
    cudaGetSymbolAddress((void**)&gab, d_gab);
    cudaGetSymbolAddress((void**)&fba, d_fba);
    cudaGetSymbolAddress((void**)&tft, d_tft);
    cudaGetSymbolAddress((void**)&tgt, d_tgt);
    cudaGetSymbolAddress((void**)&tftaa, d_tftaa);
    cudaGetSymbolAddress((void**)&tgtbb, d_tgtbb);
    cudaGetSymbolAddress((void**)&pRM, d_pRM);
    cudaGetSymbolAddress((void**)&pRS, d_pRS);
    cudaGetSymbolAddress((void**)&pCM, d_pCM);
    cudaGetSymbolAddress((void**)&pCS, d_pCS);
    cudaGetSymbolAddress((void**)&pXM, d_pXM);
    cudaGetSymbolAddress((void**)&pXS, d_pXS);
    cudaGetSymbolAddress((void**)&pYM, d_pYM);
    cudaGetSymbolAddress((void**)&pYS, d_pYS);

    const float LOGW = -logf((float)Nn);
    dim3 gg(NCH, NCH);

    sqnorm_kernel<<<1024, 256>>>(X, sqx);
    sqnorm_kernel<<<1024, 256>>>(Y, sqy);
    scale_kernel<<<1, 256>>>(sqx, sqy, scales);
    cost_gemm_kernel<<<gg, 256>>>(X, Y, sqx, sqy, scales + 3, Cxy, 0);
    cost_gemm_kernel<<<NTRI, 256>>>(X, X, sqx, sqx, scales + 4, Cxx, 1);
    cost_gemm_kernel<<<NTRI, 256>>>(Y, Y, sqy, sqy, scales + 5, Cyy, 1);

    for (int k = -1; k <= n_eps; ++k) {
        const float* ek = (k < 0) ? eps : (k < n_eps ? eps + k : eps + (n_eps - 1));
        int mode = (k < 0) ? 0 : (k < n_eps ? 1 : 2);
        int init = (k < 0) ? 1 : 0;
        tile_softmin_kernel<<<gg, 256>>>((const uint4*)Cxy, gab, fba, scales + 0,
                                         ek, LOGW, init, 0, pRM, pRS, pCM, pCS);
        tile_softmin_kernel<<<NTRI, 256>>>((const uint4*)Cxx, faa, faa, scales + 1,
                                           ek, LOGW, init, 1, pXM, pXS, pXM, pXS);
        tile_softmin_kernel<<<NTRI, 256>>>((const uint4*)Cyy, gbb, gbb, scales + 2,
                                           ek, LOGW, init, 1, pYM, pYS, pYM, pYS);
        combine_update_kernel<<<Nn / 256, 256>>>(
            pRM, pRS, pCM, pCS, pXM, pXS, pYM, pYS, ek, mode,
            faa, gbb, gab, fba, tft, tgt, tftaa, tgtbb);
    }

    final_kernel<<<1, 1024>>>(tft, tftaa, tgt, tgtbb, out);
}

// round 7
// speedup vs baseline: 1.8541x; 1.0733x over previous
#include <cuda_runtime.h>
#include <math.h>
#include <stdint.h>

typedef unsigned long long u64;
typedef unsigned int u32;
typedef unsigned short u16;

#define Nn 8192
#define NCH 64
#define NTRI (NCH * (NCH + 1) / 2)
#define NBLK (NCH * NCH + 2 * NTRI)      // 8256 merged blocks
#define L2E 1.44269504088896f
#define LN2 0.69314718055995f

// ---------------- static scratch ----------------
__device__ u16 d_Cxy[(u64)Nn * Nn];
__device__ u16 d_Cxx[(u64)Nn * Nn];   // lower-triangle tiles valid
__device__ u16 d_Cyy[(u64)Nn * Nn];
__device__ float d_sqx[Nn], d_sqy[Nn];
__device__ float d_scales[6];          // scale xy,xx,yy ; inv xy,xx,yy
__device__ float d_faa[Nn], d_gbb[Nn], d_gab[Nn], d_fba[Nn];
__device__ float d_tft[Nn], d_tgt[Nn], d_tftaa[Nn], d_tgtbb[Nn];
__device__ float d_pRM[(u64)NCH * Nn], d_pRS[(u64)NCH * Nn];
__device__ float d_pCM[(u64)NCH * Nn], d_pCS[(u64)NCH * Nn];
__device__ float d_pXM[(u64)NCH * Nn], d_pXS[(u64)NCH * Nn];
__device__ float d_pYM[(u64)NCH * Nn], d_pYS[(u64)NCH * Nn];

__device__ __forceinline__ float ex2(float x) {
    float r; asm("ex2.approx.ftz.f32 %0, %1;" : "=f"(r) : "f"(x)); return r;
}
__device__ __forceinline__ float lg2(float x) {
    float r; asm("lg2.approx.f32 %0, %1;" : "=f"(r) : "f"(x)); return r;
}
__device__ __forceinline__ void tri_decode(int b, int& by, int& bx) {
    int r = (int)((sqrtf(8.0f * (float)b + 1.0f) - 1.0f) * 0.5f);
    while ((r + 1) * (r + 2) / 2 <= b) ++r;
    while (r * (r + 1) / 2 > b) --r;
    by = r; bx = b - r * (r + 1) / 2;
}
__device__ __forceinline__ float q2f_lo(u32 a) {
    return __uint_as_float(__byte_perm(a, 0x4B000000u, 0x7410));
}
__device__ __forceinline__ float q2f_hi(u32 a) {
    return __uint_as_float(__byte_perm(a, 0x4B000000u, 0x7432));
}

// ---------------- 0.5*||row||^2 ----------------
__global__ void sqnorm_kernel(const float* __restrict__ X, float* __restrict__ sq) {
    int gw   = (blockIdx.x * blockDim.x + threadIdx.x) >> 5;
    int lane = threadIdx.x & 31;
    if (gw >= Nn) return;
    const float* xr = X + (u64)gw * 64;
    float a = xr[lane], b = xr[lane + 32];
    float s = a * a + b * b;
    #pragma unroll
    for (int o = 16; o; o >>= 1) s += __shfl_xor_sync(0xffffffffu, s, o);
    if (lane == 0) sq[gw] = 0.5f * s;
}

// ---------------- global quantization scales ----------------
__global__ void scale_kernel(const float* __restrict__ sqx, const float* __restrict__ sqy,
                             float* __restrict__ scales) {
    __shared__ float red[16];
    int tid = threadIdx.x, lane = tid & 31, w = tid >> 5;
    float mx = 0.f, my = 0.f;
    for (int i = tid; i < Nn; i += 256) {
        mx = fmaxf(mx, sqx[i]);
        my = fmaxf(my, sqy[i]);
    }
    #pragma unroll
    for (int o = 16; o; o >>= 1) {
        mx = fmaxf(mx, __shfl_xor_sync(0xffffffffu, mx, o));
        my = fmaxf(my, __shfl_xor_sync(0xffffffffu, my, o));
    }
    if (lane == 0) { red[w] = mx; red[w + 8] = my; }
    __syncthreads();
    if (tid == 0) {
        float MX = red[0], MY = red[8];
        #pragma unroll
        for (int i = 1; i < 8; ++i) { MX = fmaxf(MX, red[i]); MY = fmaxf(MY, red[8 + i]); }
        float cxy = MX + MY + 2.0f * sqrtf(MX * MY);
        float cxx = 4.0f * MX;
        float cyy = 4.0f * MY;
        scales[0] = cxy / 65500.0f; scales[3] = 65500.0f / cxy;
        scales[1] = cxx / 65500.0f; scales[4] = 65500.0f / cxx;
        scales[2] = cyy / 65500.0f; scales[5] = 65500.0f / cyy;
    }
}

// ---------------- cost GEMM (single-stage K=64, 64KB dyn smem) -> u16 ----------------
__global__ void __launch_bounds__(256, 2) cost_gemm_kernel(
    const float* __restrict__ A, const float* __restrict__ B,
    const float* __restrict__ sqa, const float* __restrict__ sqb,
    const float* __restrict__ inv_ptr, u16* __restrict__ Cq, int sym)
{
    int bxi, byi;
    if (sym) tri_decode(blockIdx.x, byi, bxi);
    else { bxi = blockIdx.x; byi = blockIdx.y; }
    extern __shared__ float sh[];
    float (*As)[128] = (float(*)[128])sh;             // [64][128]
    float (*Bs)[128] = (float(*)[128])(sh + 64 * 128);
    const int bi  = byi * 128;
    const int bj  = bxi * 128;
    const int tid = threadIdx.x;
    const int tx  = tid & 15, ty = tid >> 4;
    const float inv = *inv_ptr;

    // load full 128x64 A and B tiles (8 float4 each per thread)
    #pragma unroll
    for (int it = 0; it < 8; ++it) {
        int idx = tid + it * 256;          // 0..2047 float4 slots: row = idx>>4, kq = idx&15
        int row = idx >> 4;
        int kq  = idx & 15;
        float4 a = *(const float4*)(A + (u64)(bi + row) * 64 + kq * 4);
        float4 b = *(const float4*)(B + (u64)(bj + row) * 64 + kq * 4);
        As[kq * 4 + 0][row] = a.x; As[kq * 4 + 1][row] = a.y;
        As[kq * 4 + 2][row] = a.z; As[kq * 4 + 3][row] = a.w;
        Bs[kq * 4 + 0][row] = b.x; Bs[kq * 4 + 1][row] = b.y;
        Bs[kq * 4 + 2][row] = b.z; Bs[kq * 4 + 3][row] = b.w;
    }
    __syncthreads();

    float acc[8][8];
    #pragma unroll
    for (int r = 0; r < 8; ++r)
        #pragma unroll
        for (int c = 0; c < 8; ++c) acc[r][c] = 0.f;

    #pragma unroll 16
    for (int k = 0; k < 64; ++k) {
        float4 a0 = *(const float4*)&As[k][ty * 4];
        float4 a1 = *(const float4*)&As[k][64 + ty * 4];
        float4 b0 = *(const float4*)&Bs[k][tx * 4];
        float4 b1 = *(const float4*)&Bs[k][64 + tx * 4];
        float av[8] = {a0.x, a0.y, a0.z, a0.w, a1.x, a1.y, a1.z, a1.w};
        float bv[8] = {b0.x, b0.y, b0.z, b0.w, b1.x, b1.y, b1.z, b1.w};
        #pragma unroll
        for (int r = 0; r < 8; ++r)
            #pragma unroll
            for (int c = 0; c < 8; ++c)
                acc[r][c] = fmaf(av[r], bv[c], acc[r][c]);
    }

    #pragma unroll
    for (int rg = 0; rg < 2; ++rg)
        #pragma unroll
        for (int q = 0; q < 4; ++q) {
            int i = bi + rg * 64 + ty * 4 + q;
            float sa = sqa[i];
            int r = rg * 4 + q;
            #pragma unroll
            for (int cg = 0; cg < 2; ++cg) {
                int j0 = bj + cg * 64 + tx * 4;
                float v0 = fmaxf(sa + sqb[j0 + 0] - acc[r][cg * 4 + 0], 0.f);
                float v1 = fmaxf(sa + sqb[j0 + 1] - acc[r][cg * 4 + 1], 0.f);
                float v2 = fmaxf(sa + sqb[j0 + 2] - acc[r][cg * 4 + 2], 0.f);
                float v3 = fmaxf(sa + sqb[j0 + 3] - acc[r][cg * 4 + 3], 0.f);
                u32 b0 = __float_as_uint(fmaf(v0, inv, 8388608.0f));
                u32 b1 = __float_as_uint(fmaf(v1, inv, 8388608.0f));
                u32 b2 = __float_as_uint(fmaf(v2, inv, 8388608.0f));
                u32 b3 = __float_as_uint(fmaf(v3, inv, 8388608.0f));
                uint2 o;
                o.x = __byte_perm(b0, b1, 0x5410);
                o.y = __byte_perm(b2, b3, 0x5410);
                *(uint2*)(Cq + (u64)i * Nn + j0) = o;
            }
        }
}

// ---------------- merged tile softmin: all three matrices in ONE launch --------------
__global__ void __launch_bounds__(256, 3) tile_softmin_all_kernel(
    const uint4* __restrict__ Qxy, const uint4* __restrict__ Qxx, const uint4* __restrict__ Qyy,
    const float* __restrict__ faa, const float* __restrict__ gbb,
    const float* __restrict__ gab, const float* __restrict__ fba,
    const float* __restrict__ scales,
    const float* __restrict__ eps_ptr, float base_log, int init,
    float* __restrict__ pRM, float* __restrict__ pRS,
    float* __restrict__ pCM, float* __restrict__ pCS,
    float* __restrict__ pXM, float* __restrict__ pXS,
    float* __restrict__ pYM, float* __restrict__ pYS)
{
    int b = blockIdx.x;
    int which, bx, by;
    if (b < NCH * NCH) { which = 0; by = b >> 6; bx = b & 63; }
    else if (b < NCH * NCH + NTRI) { which = 1; tri_decode(b - NCH * NCH, by, bx); }
    else { which = 2; tri_decode(b - NCH * NCH - NTRI, by, bx); }

    const uint4* Q = (which == 0) ? Qxy : (which == 1) ? Qxx : Qyy;
    const float* potRow = (which == 0) ? gab : (which == 1) ? faa : gbb;
    const float* potCol = (which == 0) ? fba : (which == 1) ? faa : gbb;
    float* oRM = (which == 0) ? pRM : (which == 1) ? pXM : pYM;
    float* oRS = (which == 0) ? pRS : (which == 1) ? pXS : pYS;
    float* oCM = (which == 0) ? pCM : (which == 1) ? pXM : pYM;
    float* oCS = (which == 0) ? pCS : (which == 1) ? pXS : pYS;
    const bool doCol = (which == 0) || (by > bx);

    const int tid = threadIdx.x;
    const int c16 = tid & 15, rp = tid >> 4;

    const float s2   = L2E / (*eps_ptr);
    const float b2   = base_log * L2E;
    const float scs2 = scales[which] * s2;
    const float off  = b2 + 8388608.0f * scs2;

    __shared__ float gp[128];
    __shared__ float fp[128];
    __shared__ float2 part[128 * 17];

    if (tid < 128) {
        float pv = init ? 0.f : potRow[bx * 128 + tid];
        gp[tid] = fmaf(pv, s2, off);
    } else {
        int t = tid - 128;
        float pv = init ? 0.f : potCol[by * 128 + t];
        fp[t] = fmaf(pv, s2, off);
    }
    __syncthreads();

    float4 gA = *(const float4*)&gp[c16 * 8];
    float4 gB = *(const float4*)&gp[c16 * 8 + 4];
    float fpv[8];
    #pragma unroll
    for (int p = 0; p < 8; ++p) fpv[p] = fp[rp + 16 * p];

    uint4 qv[8];
    #pragma unroll
    for (int p = 0; p < 8; ++p)
        qv[p] = __ldcs(&Q[(u64)(by * 128 + rp + 16 * p) * 1024 + bx * 16 + c16]);

    const float nscs2 = -scs2;

    // ---- row phase ----
    #pragma unroll
    for (int p = 0; p < 8; ++p) {
        float v0 = fmaf(q2f_lo(qv[p].x), nscs2, gA.x);
        float v1 = fmaf(q2f_hi(qv[p].x), nscs2, gA.y);
        float v2 = fmaf(q2f_lo(qv[p].y), nscs2, gA.z);
        float v3 = fmaf(q2f_hi(qv[p].y), nscs2, gA.w);
        float v4 = fmaf(q2f_lo(qv[p].z), nscs2, gB.x);
        float v5 = fmaf(q2f_hi(qv[p].z), nscs2, gB.y);
        float v6 = fmaf(q2f_lo(qv[p].w), nscs2, gB.z);
        float v7 = fmaf(q2f_hi(qv[p].w), nscs2, gB.w);
        float m = fmaxf(fmaxf(fmaxf(v0, v1), fmaxf(v2, v3)),
                        fmaxf(fmaxf(v4, v5), fmaxf(v6, v7)));
        float s = ((ex2(v0 - m) + ex2(v1 - m)) + (ex2(v2 - m) + ex2(v3 - m)))
                + ((ex2(v4 - m) + ex2(v5 - m)) + (ex2(v6 - m) + ex2(v7 - m)));
        part[(rp + 16 * p) * 17 + c16] = make_float2(m, s);
    }
    __syncthreads();

    if (tid < 128) {
        float M = -3.4e38f;
        float2 pr[16];
        #pragma unroll
        for (int k = 0; k < 16; ++k) { pr[k] = part[tid * 17 + k]; M = fmaxf(M, pr[k].x); }
        float S = 0.f;
        #pragma unroll
        for (int k = 0; k < 16; ++k) S += pr[k].y * ex2(pr[k].x - M);
        u64 oidx = (u64)bx * Nn + by * 128 + tid;
        oRM[oidx] = M;
        oRS[oidx] = S;
    }

    // ---- col phase ----
    if (doCol) {
        __syncthreads();
        #pragma unroll
        for (int e = 0; e < 8; ++e) {
            float v[8];
            #pragma unroll
            for (int p = 0; p < 8; ++p) {
                u32 a = (e < 2) ? qv[p].x : (e < 4) ? qv[p].y : (e < 6) ? qv[p].z : qv[p].w;
                float fq = (e & 1) ? q2f_hi(a) : q2f_lo(a);
                v[p] = fmaf(fq, nscs2, fpv[p]);
            }
            float m = fmaxf(fmaxf(fmaxf(v[0], v[1]), fmaxf(v[2], v[3])),
                            fmaxf(fmaxf(v[4], v[5]), fmaxf(v[6], v[7])));
            float s = ((ex2(v[0] - m) + ex2(v[1] - m)) + (ex2(v[2] - m) + ex2(v[3] - m)))
                    + ((ex2(v[4] - m) + ex2(v[5] - m)) + (ex2(v[6] - m) + ex2(v[7] - m)));
            part[(rp * 8 + e) * 17 + c16] = make_float2(m, s);
        }
        __syncthreads();
        if (tid < 128) {
            int e = tid & 7, cc = tid >> 3;    // col = cc*8 + e
            float M = -3.4e38f;
            float2 pc[16];
            #pragma unroll
            for (int k = 0; k < 16; ++k) {
                pc[k] = part[(k * 8 + e) * 17 + cc];
                M = fmaxf(M, pc[k].x);
            }
            float S = 0.f;
            #pragma unroll
            for (int k = 0; k < 16; ++k) S += pc[k].y * ex2(pc[k].x - M);
            int col = cc * 8 + e;
            u64 oidx = (u64)by * Nn + bx * 128 + col;
            oCM[oidx] = M;
            oCS[oidx] = S;
        }
    }
}

// ---------------- combine: one output per thread, 32768 threads ----------------
__global__ void __launch_bounds__(256) combine_update_kernel(
    const float* __restrict__ pRM, const float* __restrict__ pRS,
    const float* __restrict__ pCM, const float* __restrict__ pCS,
    const float* __restrict__ pXM, const float* __restrict__ pXS,
    const float* __restrict__ pYM, const float* __restrict__ pYS,
    const float* __restrict__ eps_ptr, int mode,
    float* __restrict__ faa, float* __restrict__ gbb,
    float* __restrict__ gab, float* __restrict__ fba,
    float* __restrict__ tft, float* __restrict__ tgt,
    float* __restrict__ tftaa, float* __restrict__ tgtbb)
{
    const int gid = blockIdx.x * 256 + threadIdx.x;   // 0..32767
    const int p = gid >> 13;                          // potential index
    const int i = gid & 8191;
    const float eps = *eps_ptr;
    const float sc = -eps * LN2;

    const float* pM = (p == 0) ? pRM : (p == 1) ? pCM : (p == 2) ? pXM : pYM;
    const float* pS = (p == 0) ? pRS : (p == 1) ? pCS : (p == 2) ? pXS : pYS;

    float M = -3.4e38f;
    #pragma unroll 16
    for (int c = 0; c < NCH; ++c) M = fmaxf(M, pM[(u64)c * Nn + i]);
    float S = 0.f;
    #pragma unroll 16
    for (int c = 0; c < NCH; ++c) S += pS[(u64)c * Nn + i] * ex2(pM[(u64)c * Nn + i] - M);
    float v = sc * (lg2(S) + M);

    float* dstA = (p == 0) ? fba : (p == 1) ? gab : (p == 2) ? faa : gbb;
    float* dstT = (p == 0) ? tft : (p == 1) ? tgt : (p == 2) ? tftaa : tgtbb;

    if (mode == 0)       dstA[i] = v;
    else if (mode == 1)  dstA[i] = 0.5f * (dstA[i] + v);
    else                 dstT[i] = v;
}

// ---------------- final scalar ----------------
__global__ void final_kernel(const float* __restrict__ fbaf, const float* __restrict__ faaf,
                             const float* __restrict__ gabf, const float* __restrict__ gbbf,
                             float* __restrict__ out)
{
    __shared__ float red[32];
    int tid = threadIdx.x;
    int lane = tid & 31, wid = tid >> 5;
    float s = 0.f;
    for (int i = tid; i < Nn; i += 1024)
        s += (fbaf[i] - faaf[i]) + (gabf[i] - gbbf[i]);
    #pragma unroll
    for (int o = 16; o; o >>= 1) s += __shfl_xor_sync(0xffffffffu, s, o);
    if (lane == 0) red[wid] = s;
    __syncthreads();
    if (wid == 0) {
        float v = red[lane];
        #pragma unroll
        for (int o = 16; o; o >>= 1) v += __shfl_xor_sync(0xffffffffu, v, o);
        if (lane == 0) out[0] = v / (float)Nn;
    }
}

// ---------------- launch ----------------
extern "C" void kernel_launch(void* const* d_in, const int* in_sizes, int n_in,
                              void* d_out, int out_size)
{
    const float* X   = (const float*)d_in[0];
    const float* Y   = (const float*)d_in[1];
    const float* eps = (const float*)d_in[2];
    const int n_eps  = in_sizes[2];
    float* out = (float*)d_out;

    u16 *Cxy, *Cxx, *Cyy;
    float *sqx, *sqy, *scales;
    float *faa, *gbb, *gab, *fba, *tft, *tgt, *tftaa, *tgtbb;
    float *pRM, *pRS, *pCM, *pCS, *pXM, *pXS, *pYM, *pYS;
    cudaGetSymbolAddress((void**)&Cxy, d_Cxy);
    cudaGetSymbolAddress((void**)&Cxx, d_Cxx);
    cudaGetSymbolAddress((void**)&Cyy, d_Cyy);
    cudaGetSymbolAddress((void**)&sqx, d_sqx);
    cudaGetSymbolAddress((void**)&sqy, d_sqy);
    cudaGetSymbolAddress((void**)&scales, d_scales);
    cudaGetSymbolAddress((void**)&faa, d_faa);
    cudaGetSymbolAddress((void**)&gbb, d_gbb);
    cudaGetSymbolAddress((void**)&gab, d_gab);
    cudaGetSymbolAddress((void**)&fba, d_fba);
    cudaGetSymbolAddress((void**)&tft, d_tft);
    cudaGetSymbolAddress((void**)&tgt, d_tgt);
    cudaGetSymbolAddress((void**)&tftaa, d_tftaa);
    cudaGetSymbolAddress((void**)&tgtbb, d_tgtbb);
    cudaGetSymbolAddress((void**)&pRM, d_pRM);
    cudaGetSymbolAddress((void**)&pRS, d_pRS);
    cudaGetSymbolAddress((void**)&pCM, d_pCM);
    cudaGetSymbolAddress((void**)&pCS, d_pCS);
    cudaGetSymbolAddress((void**)&pXM, d_pXM);
    cudaGetSymbolAddress((void**)&pXS, d_pXS);
    cudaGetSymbolAddress((void**)&pYM, d_pYM);
    cudaGetSymbolAddress((void**)&pYS, d_pYS);

    cudaFuncSetAttribute(cost_gemm_kernel,
                         cudaFuncAttributeMaxDynamicSharedMemorySize, 65536);

    const float LOGW = -logf((float)Nn);
    dim3 gg(NCH, NCH);

    sqnorm_kernel<<<1024, 256>>>(X, sqx);
    sqnorm_kernel<<<1024, 256>>>(Y, sqy);
    scale_kernel<<<1, 256>>>(sqx, sqy, scales);
    cost_gemm_kernel<<<gg, 256, 65536>>>(X, Y, sqx, sqy, scales + 3, Cxy, 0);
    cost_gemm_kernel<<<NTRI, 256, 65536>>>(X, X, sqx, sqx, scales + 4, Cxx, 1);
    cost_gemm_kernel<<<NTRI, 256, 65536>>>(Y, Y, sqy, sqy, scales + 5, Cyy, 1);

    for (int k = -1; k <= n_eps; ++k) {
        const float* ek = (k < 0) ? eps : (k < n_eps ? eps + k : eps + (n_eps - 1));
        int mode = (k < 0) ? 0 : (k < n_eps ? 1 : 2);
        int init = (k < 0) ? 1 : 0;
        tile_softmin_all_kernel<<<NBLK, 256>>>(
            (const uint4*)Cxy, (const uint4*)Cxx, (const uint4*)Cyy,
            faa, gbb, gab, fba, scales, ek, LOGW, init,
            pRM, pRS, pCM, pCS, pXM, pXS, pYM, pYS);
        combine_update_kernel<<<128, 256>>>(
            pRM, pRS, pCM, pCS, pXM, pXS, pYM, pYS, ek, mode,
            faa, gbb, gab, fba, tft, tgt, tftaa, tgtbb);
    }

    final_kernel<<<1, 1024>>>(tft, tftaa, tgt, tgtbb, out);
}

// round 8
// speedup vs baseline: 2.2001x; 1.1866x over previous
#include <cuda_runtime.h>
#include <math.h>
#include <stdint.h>

typedef unsigned long long u64;
typedef unsigned int u32;
typedef unsigned short u16;

#define Nn 8192
#define NCH 64
#define NTRI (NCH * (NCH + 1) / 2)
#define NBLK (NCH * NCH + 2 * NTRI)      // 8256 merged blocks
#define L2E 1.44269504088896f
#define LN2 0.69314718055995f

// ---------------- static scratch ----------------
__device__ u16 d_Cxy[(u64)Nn * Nn];
__device__ u16 d_Cxx[(u64)Nn * Nn];   // lower-triangle tiles valid
__device__ u16 d_Cyy[(u64)Nn * Nn];
__device__ float d_sqx[Nn], d_sqy[Nn];
__device__ float d_scales[6];          // scale xy,xx,yy ; inv xy,xx,yy
__device__ float d_faa[Nn], d_gbb[Nn], d_gab[Nn], d_fba[Nn];
__device__ float d_tft[Nn], d_tgt[Nn], d_tftaa[Nn], d_tgtbb[Nn];
__device__ float d_pRM[(u64)NCH * Nn], d_pRS[(u64)NCH * Nn];
__device__ float d_pCM[(u64)NCH * Nn], d_pCS[(u64)NCH * Nn];
__device__ float d_pXM[(u64)NCH * Nn], d_pXS[(u64)NCH * Nn];
__device__ float d_pYM[(u64)NCH * Nn], d_pYS[(u64)NCH * Nn];

__device__ __forceinline__ float ex2(float x) {
    float r; asm("ex2.approx.ftz.f32 %0, %1;" : "=f"(r) : "f"(x)); return r;
}
__device__ __forceinline__ float lg2(float x) {
    float r; asm("lg2.approx.f32 %0, %1;" : "=f"(r) : "f"(x)); return r;
}
__device__ __forceinline__ void tri_decode(int b, int& by, int& bx) {
    int r = (int)((sqrtf(8.0f * (float)b + 1.0f) - 1.0f) * 0.5f);
    while ((r + 1) * (r + 2) / 2 <= b) ++r;
    while (r * (r + 1) / 2 > b) --r;
    by = r; bx = b - r * (r + 1) / 2;
}
__device__ __forceinline__ float q2f_lo(u32 a) {
    return __uint_as_float(__byte_perm(a, 0x4B000000u, 0x7410));
}
__device__ __forceinline__ float q2f_hi(u32 a) {
    return __uint_as_float(__byte_perm(a, 0x4B000000u, 0x7432));
}

// ---------------- 0.5*||row||^2 ----------------
__global__ void sqnorm_kernel(const float* __restrict__ X, float* __restrict__ sq) {
    int gw   = (blockIdx.x * blockDim.x + threadIdx.x) >> 5;
    int lane = threadIdx.x & 31;
    if (gw >= Nn) return;
    const float* xr = X + (u64)gw * 64;
    float a = xr[lane], b = xr[lane + 32];
    float s = a * a + b * b;
    #pragma unroll
    for (int o = 16; o; o >>= 1) s += __shfl_xor_sync(0xffffffffu, s, o);
    if (lane == 0) sq[gw] = 0.5f * s;
}

// ---------------- global quantization scales ----------------
__global__ void scale_kernel(const float* __restrict__ sqx, const float* __restrict__ sqy,
                             float* __restrict__ scales) {
    __shared__ float red[16];
    int tid = threadIdx.x, lane = tid & 31, w = tid >> 5;
    float mx = 0.f, my = 0.f;
    for (int i = tid; i < Nn; i += 256) {
        mx = fmaxf(mx, sqx[i]);
        my = fmaxf(my, sqy[i]);
    }
    #pragma unroll
    for (int o = 16; o; o >>= 1) {
        mx = fmaxf(mx, __shfl_xor_sync(0xffffffffu, mx, o));
        my = fmaxf(my, __shfl_xor_sync(0xffffffffu, my, o));
    }
    if (lane == 0) { red[w] = mx; red[w + 8] = my; }
    __syncthreads();
    if (tid == 0) {
        float MX = red[0], MY = red[8];
        #pragma unroll
        for (int i = 1; i < 8; ++i) { MX = fmaxf(MX, red[i]); MY = fmaxf(MY, red[8 + i]); }
        float cxy = MX + MY + 2.0f * sqrtf(MX * MY);
        float cxx = 4.0f * MX;
        float cyy = 4.0f * MY;
        scales[0] = cxy / 65500.0f; scales[3] = 65500.0f / cxy;
        scales[1] = cxx / 65500.0f; scales[4] = 65500.0f / cxx;
        scales[2] = cyy / 65500.0f; scales[5] = 65500.0f / cyy;
    }
}

// ---------------- cost GEMM (two-stage K=32) -> quantized u16 ----------------
__global__ void __launch_bounds__(256, 2) cost_gemm_kernel(
    const float* __restrict__ A, const float* __restrict__ B,
    const float* __restrict__ sqa, const float* __restrict__ sqb,
    const float* __restrict__ inv_ptr, u16* __restrict__ Cq, int sym)
{
    int bxi, byi;
    if (sym) tri_decode(blockIdx.x, byi, bxi);
    else { bxi = blockIdx.x; byi = blockIdx.y; }
    __shared__ float As[32][128];
    __shared__ float Bs[32][128];
    const int bi  = byi * 128;
    const int bj  = bxi * 128;
    const int tid = threadIdx.x;
    const int tx  = tid & 15, ty = tid >> 4;
    const float inv = *inv_ptr;

    float acc[8][8];
    #pragma unroll
    for (int r = 0; r < 8; ++r)
        #pragma unroll
        for (int c = 0; c < 8; ++c) acc[r][c] = 0.f;

    for (int kc = 0; kc < 64; kc += 32) {
        #pragma unroll
        for (int it = 0; it < 4; ++it) {
            int idx = tid + it * 256;
            int row = idx >> 3;
            int kq  = idx & 7;
            float4 a = *(const float4*)(A + (u64)(bi + row) * 64 + kc + kq * 4);
            float4 b = *(const float4*)(B + (u64)(bj + row) * 64 + kc + kq * 4);
            As[kq * 4 + 0][row] = a.x; As[kq * 4 + 1][row] = a.y;
            As[kq * 4 + 2][row] = a.z; As[kq * 4 + 3][row] = a.w;
            Bs[kq * 4 + 0][row] = b.x; Bs[kq * 4 + 1][row] = b.y;
            Bs[kq * 4 + 2][row] = b.z; Bs[kq * 4 + 3][row] = b.w;
        }
        __syncthreads();
        #pragma unroll
        for (int k = 0; k < 32; ++k) {
            float4 a0 = *(const float4*)&As[k][ty * 4];
            float4 a1 = *(const float4*)&As[k][64 + ty * 4];
            float4 b0 = *(const float4*)&Bs[k][tx * 4];
            float4 b1 = *(const float4*)&Bs[k][64 + tx * 4];
            float av[8] = {a0.x, a0.y, a0.z, a0.w, a1.x, a1.y, a1.z, a1.w};
            float bv[8] = {b0.x, b0.y, b0.z, b0.w, b1.x, b1.y, b1.z, b1.w};
            #pragma unroll
            for (int r = 0; r < 8; ++r)
                #pragma unroll
                for (int c = 0; c < 8; ++c)
                    acc[r][c] = fmaf(av[r], bv[c], acc[r][c]);
        }
        __syncthreads();
    }

    #pragma unroll
    for (int rg = 0; rg < 2; ++rg)
        #pragma unroll
        for (int q = 0; q < 4; ++q) {
            int i = bi + rg * 64 + ty * 4 + q;
            float sa = sqa[i];
            int r = rg * 4 + q;
            #pragma unroll
            for (int cg = 0; cg < 2; ++cg) {
                int j0 = bj + cg * 64 + tx * 4;
                float v0 = fmaxf(sa + sqb[j0 + 0] - acc[r][cg * 4 + 0], 0.f);
                float v1 = fmaxf(sa + sqb[j0 + 1] - acc[r][cg * 4 + 1], 0.f);
                float v2 = fmaxf(sa + sqb[j0 + 2] - acc[r][cg * 4 + 2], 0.f);
                float v3 = fmaxf(sa + sqb[j0 + 3] - acc[r][cg * 4 + 3], 0.f);
                u32 b0 = __float_as_uint(fmaf(v0, inv, 8388608.0f));
                u32 b1 = __float_as_uint(fmaf(v1, inv, 8388608.0f));
                u32 b2 = __float_as_uint(fmaf(v2, inv, 8388608.0f));
                u32 b3 = __float_as_uint(fmaf(v3, inv, 8388608.0f));
                uint2 o;
                o.x = __byte_perm(b0, b1, 0x5410);
                o.y = __byte_perm(b2, b3, 0x5410);
                *(uint2*)(Cq + (u64)i * Nn + j0) = o;
            }
        }
}

// ---------------- merged tile softmin: all three matrices in ONE launch --------------
__global__ void __launch_bounds__(256, 3) tile_softmin_all_kernel(
    const uint4* __restrict__ Qxy, const uint4* __restrict__ Qxx, const uint4* __restrict__ Qyy,
    const float* __restrict__ faa, const float* __restrict__ gbb,
    const float* __restrict__ gab, const float* __restrict__ fba,
    const float* __restrict__ scales,
    const float* __restrict__ eps_ptr, float base_log, int init,
    float* __restrict__ pRM, float* __restrict__ pRS,
    float* __restrict__ pCM, float* __restrict__ pCS,
    float* __restrict__ pXM, float* __restrict__ pXS,
    float* __restrict__ pYM, float* __restrict__ pYS)
{
    int b = blockIdx.x;
    int which, bx, by;
    if (b < NCH * NCH) { which = 0; by = b >> 6; bx = b & 63; }
    else if (b < NCH * NCH + NTRI) { which = 1; tri_decode(b - NCH * NCH, by, bx); }
    else { which = 2; tri_decode(b - NCH * NCH - NTRI, by, bx); }

    const uint4* Q = (which == 0) ? Qxy : (which == 1) ? Qxx : Qyy;
    const float* potRow = (which == 0) ? gab : (which == 1) ? faa : gbb;
    const float* potCol = (which == 0) ? fba : (which == 1) ? faa : gbb;
    float* oRM = (which == 0) ? pRM : (which == 1) ? pXM : pYM;
    float* oRS = (which == 0) ? pRS : (which == 1) ? pXS : pYS;
    float* oCM = (which == 0) ? pCM : (which == 1) ? pXM : pYM;
    float* oCS = (which == 0) ? pCS : (which == 1) ? pXS : pYS;
    const bool doCol = (which == 0) || (by > bx);

    const int tid = threadIdx.x;
    const int c16 = tid & 15, rp = tid >> 4;

    const float s2   = L2E / (*eps_ptr);
    const float b2   = base_log * L2E;
    const float scs2 = scales[which] * s2;
    const float off  = b2 + 8388608.0f * scs2;

    __shared__ float gp[128];
    __shared__ float fp[128];
    __shared__ float2 part[128 * 17];

    // issue global tile loads FIRST (independent of smem), overlap with pot setup
    uint4 qv[8];
    #pragma unroll
    for (int p = 0; p < 8; ++p)
        qv[p] = __ldcs(&Q[(u64)(by * 128 + rp + 16 * p) * 1024 + bx * 16 + c16]);

    if (tid < 128) {
        float pv = init ? 0.f : potRow[bx * 128 + tid];
        gp[tid] = fmaf(pv, s2, off);
    } else {
        int t = tid - 128;
        float pv = init ? 0.f : potCol[by * 128 + t];
        fp[t] = fmaf(pv, s2, off);
    }
    __syncthreads();

    float4 gA = *(const float4*)&gp[c16 * 8];
    float4 gB = *(const float4*)&gp[c16 * 8 + 4];
    float fpv[8];
    #pragma unroll
    for (int p = 0; p < 8; ++p) fpv[p] = fp[rp + 16 * p];

    const float nscs2 = -scs2;

    // ---- row phase ----
    #pragma unroll
    for (int p = 0; p < 8; ++p) {
        float v0 = fmaf(q2f_lo(qv[p].x), nscs2, gA.x);
        float v1 = fmaf(q2f_hi(qv[p].x), nscs2, gA.y);
        float v2 = fmaf(q2f_lo(qv[p].y), nscs2, gA.z);
        float v3 = fmaf(q2f_hi(qv[p].y), nscs2, gA.w);
        float v4 = fmaf(q2f_lo(qv[p].z), nscs2, gB.x);
        float v5 = fmaf(q2f_hi(qv[p].z), nscs2, gB.y);
        float v6 = fmaf(q2f_lo(qv[p].w), nscs2, gB.z);
        float v7 = fmaf(q2f_hi(qv[p].w), nscs2, gB.w);
        float m = fmaxf(fmaxf(fmaxf(v0, v1), fmaxf(v2, v3)),
                        fmaxf(fmaxf(v4, v5), fmaxf(v6, v7)));
        float s = ((ex2(v0 - m) + ex2(v1 - m)) + (ex2(v2 - m) + ex2(v3 - m)))
                + ((ex2(v4 - m) + ex2(v5 - m)) + (ex2(v6 - m) + ex2(v7 - m)));
        part[(rp + 16 * p) * 17 + c16] = make_float2(m, s);
    }
    __syncthreads();

    if (tid < 128) {
        float M = -3.4e38f;
        float2 pr[16];
        #pragma unroll
        for (int k = 0; k < 16; ++k) { pr[k] = part[tid * 17 + k]; M = fmaxf(M, pr[k].x); }
        float S = 0.f;
        #pragma unroll
        for (int k = 0; k < 16; ++k) S += pr[k].y * ex2(pr[k].x - M);
        u64 oidx = (u64)bx * Nn + by * 128 + tid;
        oRM[oidx] = M;
        oRS[oidx] = S;
    }

    // ---- col phase ----
    if (doCol) {
        __syncthreads();
        #pragma unroll
        for (int e = 0; e < 8; ++e) {
            float v[8];
            #pragma unroll
            for (int p = 0; p < 8; ++p) {
                u32 a = (e < 2) ? qv[p].x : (e < 4) ? qv[p].y : (e < 6) ? qv[p].z : qv[p].w;
                float fq = (e & 1) ? q2f_hi(a) : q2f_lo(a);
                v[p] = fmaf(fq, nscs2, fpv[p]);
            }
            float m = fmaxf(fmaxf(fmaxf(v[0], v[1]), fmaxf(v[2], v[3])),
                            fmaxf(fmaxf(v[4], v[5]), fmaxf(v[6], v[7])));
            float s = ((ex2(v[0] - m) + ex2(v[1] - m)) + (ex2(v[2] - m) + ex2(v[3] - m)))
                    + ((ex2(v[4] - m) + ex2(v[5] - m)) + (ex2(v[6] - m) + ex2(v[7] - m)));
            part[(rp * 8 + e) * 17 + c16] = make_float2(m, s);
        }
        __syncthreads();
        if (tid < 128) {
            int e = tid & 7, cc = tid >> 3;    // col = cc*8 + e
            float M = -3.4e38f;
            float2 pc[16];
            #pragma unroll
            for (int k = 0; k < 16; ++k) {
                pc[k] = part[(k * 8 + e) * 17 + cc];
                M = fmaxf(M, pc[k].x);
            }
            float S = 0.f;
            #pragma unroll
            for (int k = 0; k < 16; ++k) S += pc[k].y * ex2(pc[k].x - M);
            int col = cc * 8 + e;
            u64 oidx = (u64)by * Nn + bx * 128 + col;
            oCM[oidx] = M;
            oCS[oidx] = S;
        }
    }
}

// ---------------- combine: one output per thread, 32768 threads ----------------
__global__ void __launch_bounds__(256) combine_update_kernel(
    const float* __restrict__ pRM, const float* __restrict__ pRS,
    const float* __restrict__ pCM, const float* __restrict__ pCS,
    const float* __restrict__ pXM, const float* __restrict__ pXS,
    const float* __restrict__ pYM, const float* __restrict__ pYS,
    const float* __restrict__ eps_ptr, int mode,
    float* __restrict__ faa, float* __restrict__ gbb,
    float* __restrict__ gab, float* __restrict__ fba,
    float* __restrict__ tft, float* __restrict__ tgt,
    float* __restrict__ tftaa, float* __restrict__ tgtbb)
{
    const int gid = blockIdx.x * 256 + threadIdx.x;   // 0..32767
    const int p = gid >> 13;                          // potential index
    const int i = gid & 8191;
    const float eps = *eps_ptr;
    const float sc = -eps * LN2;

    const float* pM = (p == 0) ? pRM : (p == 1) ? pCM : (p == 2) ? pXM : pYM;
    const float* pS = (p == 0) ? pRS : (p == 1) ? pCS : (p == 2) ? pXS : pYS;

    float M = -3.4e38f;
    #pragma unroll 16
    for (int c = 0; c < NCH; ++c) M = fmaxf(M, pM[(u64)c * Nn + i]);
    float S = 0.f;
    #pragma unroll 16
    for (int c = 0; c < NCH; ++c) S += pS[(u64)c * Nn + i] * ex2(pM[(u64)c * Nn + i] - M);
    float v = sc * (lg2(S) + M);

    float* dstA = (p == 0) ? fba : (p == 1) ? gab : (p == 2) ? faa : gbb;
    float* dstT = (p == 0) ? tft : (p == 1) ? tgt : (p == 2) ? tftaa : tgtbb;

    if (mode == 0)       dstA[i] = v;
    else if (mode == 1)  dstA[i] = 0.5f * (dstA[i] + v);
    else                 dstT[i] = v;
}

// ---------------- final scalar ----------------
__global__ void final_kernel(const float* __restrict__ fbaf, const float* __restrict__ faaf,
                             const float* __restrict__ gabf, const float* __restrict__ gbbf,
                             float* __restrict__ out)
{
    __shared__ float red[32];
    int tid = threadIdx.x;
    int lane = tid & 31, wid = tid >> 5;
    float s = 0.f;
    for (int i = tid; i < Nn; i += 1024)
        s += (fbaf[i] - faaf[i]) + (gabf[i] - gbbf[i]);
    #pragma unroll
    for (int o = 16; o; o >>= 1) s += __shfl_xor_sync(0xffffffffu, s, o);
    if (lane == 0) red[wid] = s;
    __syncthreads();
    if (wid == 0) {
        float v = red[lane];
        #pragma unroll
        for (int o = 16; o; o >>= 1) v += __shfl_xor_sync(0xffffffffu, v, o);
        if (lane == 0) out[0] = v / (float)Nn;
    }
}

// ---------------- launch ----------------
extern "C" void kernel_launch(void* const* d_in, const int* in_sizes, int n_in,
                              void* d_out, int out_size)
{
    const float* X   = (const float*)d_in[0];
    const float* Y   = (const float*)d_in[1];
    const float* eps = (const float*)d_in[2];
    const int n_eps  = in_sizes[2];
    float* out = (float*)d_out;

    u16 *Cxy, *Cxx, *Cyy;
    float *sqx, *sqy, *scales;
    float *faa, *gbb, *gab, *fba, *tft, *tgt, *tftaa, *tgtbb;
    float *pRM, *pRS, *pCM, *pCS, *pXM, *pXS, *pYM, *pYS;
    cudaGetSymbolAddress((void**)&Cxy, d_Cxy);
    cudaGetSymbolAddress((void**)&Cxx, d_Cxx);
    cudaGetSymbolAddress((void**)&Cyy, d_Cyy);
    cudaGetSymbolAddress((void**)&sqx, d_sqx);
    cudaGetSymbolAddress((void**)&sqy, d_sqy);
    cudaGetSymbolAddress((void**)&scales, d_scales);
    cudaGetSymbolAddress((void**)&faa, d_faa);
    cudaGetSymbolAddress((void**)&gbb, d_gbb);
    cudaGetSymbolAddress((void**)&gab, d_gab);
    cudaGetSymbolAddress((void**)&fba, d_fba);
    cudaGetSymbolAddress((void**)&tft, d_tft);
    cudaGetSymbolAddress((void**)&tgt, d_tgt);
    cudaGetSymbolAddress((void**)&tftaa, d_tftaa);
    cudaGetSymbolAddress((void**)&tgtbb, d_tgtbb);
    cudaGetSymbolAddress((void**)&pRM, d_pRM);
    cudaGetSymbolAddress((void**)&pRS, d_pRS);
    cudaGetSymbolAddress((void**)&pCM, d_pCM);
    cudaGetSymbolAddress((void**)&pCS, d_pCS);
    cudaGetSymbolAddress((void**)&pXM, d_pXM);
    cudaGetSymbolAddress((void**)&pXS, d_pXS);
    cudaGetSymbolAddress((void**)&pYM, d_pYM);
    cudaGetSymbolAddress((void**)&pYS, d_pYS);

    const float LOGW = -logf((float)Nn);
    dim3 gg(NCH, NCH);

    sqnorm_kernel<<<1024, 256>>>(X, sqx);
    sqnorm_kernel<<<1024, 256>>>(Y, sqy);
    scale_kernel<<<1, 256>>>(sqx, sqy, scales);
    cost_gemm_kernel<<<gg, 256>>>(X, Y, sqx, sqy, scales + 3, Cxy, 0);
    cost_gemm_kernel<<<NTRI, 256>>>(X, X, sqx, sqx, scales + 4, Cxx, 1);
    cost_gemm_kernel<<<NTRI, 256>>>(Y, Y, sqy, sqy, scales + 5, Cyy, 1);

    for (int k = -1; k <= n_eps; ++k) {
        const float* ek = (k < 0) ? eps : (k < n_eps ? eps + k : eps + (n_eps - 1));
        int mode = (k < 0) ? 0 : (k < n_eps ? 1 : 2);
        int init = (k < 0) ? 1 : 0;
        tile_softmin_all_kernel<<<NBLK, 256>>>(
            (const uint4*)Cxy, (const uint4*)Cxx, (const uint4*)Cyy,
            faa, gbb, gab, fba, scales, ek, LOGW, init,
            pRM, pRS, pCM, pCS, pXM, pXS, pYM, pYS);
        combine_update_kernel<<<128, 256>>>(
            pRM, pRS, pCM, pCS, pXM, pXS, pYM, pYS, ek, mode,
            faa, gbb, gab, fba, tft, tgt, tftaa, tgtbb);
    }

    final_kernel<<<1, 1024>>>(tft, tftaa, tgt, tgtbb, out);
}

// round 9
// speedup vs baseline: 2.5504x; 1.1593x over previous
#include <cuda_runtime.h>
#include <cuda_bf16.h>
#include <math.h>
#include <stdint.h>

typedef unsigned long long u64;
typedef unsigned int u32;
typedef unsigned short u16;

#define Nn 8192
#define NCH 64
#define NTRI (NCH * (NCH + 1) / 2)
#define NBLK (NCH * NCH + 2 * NTRI)      // 8256 merged blocks
#define L2E 1.44269504088896f
#define LN2 0.69314718055995f

// ---------------- static scratch ----------------
__device__ u16 d_Cxy[(u64)Nn * Nn];
__device__ u16 d_Cxx[(u64)Nn * Nn];   // lower-triangle tiles valid
__device__ u16 d_Cyy[(u64)Nn * Nn];
__device__ __nv_bfloat16 d_Xh[(u64)Nn * 64], d_Xl[(u64)Nn * 64];
__device__ __nv_bfloat16 d_Yh[(u64)Nn * 64], d_Yl[(u64)Nn * 64];
__device__ float d_sqx[Nn], d_sqy[Nn];
__device__ float d_scales[6];          // scale xy,xx,yy ; inv xy,xx,yy
__device__ float d_faa[Nn], d_gbb[Nn], d_gab[Nn], d_fba[Nn];
__device__ float d_tft[Nn], d_tgt[Nn], d_tftaa[Nn], d_tgtbb[Nn];
__device__ float d_pRM[(u64)NCH * Nn], d_pRS[(u64)NCH * Nn];
__device__ float d_pCM[(u64)NCH * Nn], d_pCS[(u64)NCH * Nn];
__device__ float d_pXM[(u64)NCH * Nn], d_pXS[(u64)NCH * Nn];
__device__ float d_pYM[(u64)NCH * Nn], d_pYS[(u64)NCH * Nn];

__device__ __forceinline__ float ex2(float x) {
    float r; asm("ex2.approx.ftz.f32 %0, %1;" : "=f"(r) : "f"(x)); return r;
}
__device__ __forceinline__ float lg2(float x) {
    float r; asm("lg2.approx.f32 %0, %1;" : "=f"(r) : "f"(x)); return r;
}
__device__ __forceinline__ void tri_decode(int b, int& by, int& bx) {
    int r = (int)((sqrtf(8.0f * (float)b + 1.0f) - 1.0f) * 0.5f);
    while ((r + 1) * (r + 2) / 2 <= b) ++r;
    while (r * (r + 1) / 2 > b) --r;
    by = r; bx = b - r * (r + 1) / 2;
}
__device__ __forceinline__ float q2f_lo(u32 a) {
    return __uint_as_float(__byte_perm(a, 0x4B000000u, 0x7410));
}
__device__ __forceinline__ float q2f_hi(u32 a) {
    return __uint_as_float(__byte_perm(a, 0x4B000000u, 0x7432));
}
__device__ __forceinline__ void ldsm4(u32& r0, u32& r1, u32& r2, u32& r3, u32 addr) {
    asm volatile("ldmatrix.sync.aligned.m8n8.x4.shared.b16 {%0,%1,%2,%3}, [%4];"
                 : "=r"(r0), "=r"(r1), "=r"(r2), "=r"(r3) : "r"(addr));
}
__device__ __forceinline__ void mma16816(float* d, const u32* a, u32 b0, u32 b1) {
    asm volatile(
        "mma.sync.aligned.m16n8k16.row.col.f32.bf16.bf16.f32 "
        "{%0,%1,%2,%3}, {%4,%5,%6,%7}, {%8,%9}, {%0,%1,%2,%3};"
        : "+f"(d[0]), "+f"(d[1]), "+f"(d[2]), "+f"(d[3])
        : "r"(a[0]), "r"(a[1]), "r"(a[2]), "r"(a[3]), "r"(b0), "r"(b1));
}

// ---------------- 0.5*||row||^2 ----------------
__global__ void sqnorm_kernel(const float* __restrict__ X, float* __restrict__ sq) {
    int gw   = (blockIdx.x * blockDim.x + threadIdx.x) >> 5;
    int lane = threadIdx.x & 31;
    if (gw >= Nn) return;
    const float* xr = X + (u64)gw * 64;
    float a = xr[lane], b = xr[lane + 32];
    float s = a * a + b * b;
    #pragma unroll
    for (int o = 16; o; o >>= 1) s += __shfl_xor_sync(0xffffffffu, s, o);
    if (lane == 0) sq[gw] = 0.5f * s;
}

// ---------------- fp32 -> bf16 hi/lo split ----------------
__global__ void split_kernel(const float* __restrict__ X,
                             __nv_bfloat16* __restrict__ hi, __nv_bfloat16* __restrict__ lo) {
    int i = blockIdx.x * 256 + threadIdx.x;
    float x = X[i];
    __nv_bfloat16 h = __float2bfloat16(x);
    hi[i] = h;
    lo[i] = __float2bfloat16(x - __bfloat162float(h));
}

// ---------------- global quantization scales ----------------
__global__ void scale_kernel(const float* __restrict__ sqx, const float* __restrict__ sqy,
                             float* __restrict__ scales) {
    __shared__ float red[16];
    int tid = threadIdx.x, lane = tid & 31, w = tid >> 5;
    float mx = 0.f, my = 0.f;
    for (int i = tid; i < Nn; i += 256) {
        mx = fmaxf(mx, sqx[i]);
        my = fmaxf(my, sqy[i]);
    }
    #pragma unroll
    for (int o = 16; o; o >>= 1) {
        mx = fmaxf(mx, __shfl_xor_sync(0xffffffffu, mx, o));
        my = fmaxf(my, __shfl_xor_sync(0xffffffffu, my, o));
    }
    if (lane == 0) { red[w] = mx; red[w + 8] = my; }
    __syncthreads();
    if (tid == 0) {
        float MX = red[0], MY = red[8];
        #pragma unroll
        for (int i = 1; i < 8; ++i) { MX = fmaxf(MX, red[i]); MY = fmaxf(MY, red[8 + i]); }
        float cxy = MX + MY + 2.0f * sqrtf(MX * MY);
        float cxx = 4.0f * MX;
        float cyy = 4.0f * MY;
        scales[0] = cxy / 65500.0f; scales[3] = 65500.0f / cxy;
        scales[1] = cxx / 65500.0f; scales[4] = 65500.0f / cxx;
        scales[2] = cyy / 65500.0f; scales[5] = 65500.0f / cyy;
    }
}

// ---------------- tensor-core cost GEMM (bf16 3-term split) -> quantized u16 --------
// CTA 128x128, 8 warps each m32 x n64, K=64 staged once in 64KB smem (16B-chunk XOR
// swizzle), 4 k16 steps. D = A.B^T via hi*hi + lo*hi + hi*lo, fp32 accumulate.
__global__ void __launch_bounds__(256, 2) mma_cost_gemm_kernel(
    const __nv_bfloat16* __restrict__ Ah_g, const __nv_bfloat16* __restrict__ Al_g,
    const __nv_bfloat16* __restrict__ Bh_g, const __nv_bfloat16* __restrict__ Bl_g,
    const float* __restrict__ sqa, const float* __restrict__ sqb,
    const float* __restrict__ inv_ptr, u16* __restrict__ Cq, int sym)
{
    int bxi, byi;
    if (sym) tri_decode(blockIdx.x, byi, bxi);
    else { bxi = blockIdx.x; byi = blockIdx.y; }
    const int bi = byi * 128, bj = bxi * 128;
    extern __shared__ __nv_bfloat16 sh[];
    __nv_bfloat16* sAh = sh;
    __nv_bfloat16* sAl = sh + 8192;
    __nv_bfloat16* sBh = sh + 16384;
    __nv_bfloat16* sBl = sh + 24576;
    const int tid = threadIdx.x;
    const float inv = *inv_ptr;

    #pragma unroll
    for (int i = 0; i < 4; ++i) {
        int idx = tid + i * 256;           // 0..1023 chunks: r = idx>>3, c = idx&7
        int r = idx >> 3, c = idx & 7;
        int sc = c ^ (r & 7);
        ((uint4*)sAh)[r * 8 + sc] = *(const uint4*)(Ah_g + (u64)(bi + r) * 64 + c * 8);
        ((uint4*)sAl)[r * 8 + sc] = *(const uint4*)(Al_g + (u64)(bi + r) * 64 + c * 8);
        ((uint4*)sBh)[r * 8 + sc] = *(const uint4*)(Bh_g + (u64)(bj + r) * 64 + c * 8);
        ((uint4*)sBl)[r * 8 + sc] = *(const uint4*)(Bl_g + (u64)(bj + r) * 64 + c * 8);
    }
    __syncthreads();

    const int w = tid >> 5, lane = tid & 31;
    const int mw = (w & 3) * 32, nw = (w >> 2) * 64;
    const int lq = lane >> 3, lr = lane & 7;      // ldmatrix: matrix idx, row-in-matrix
    const u32 baseAh = (u32)__cvta_generic_to_shared(sAh);
    const u32 baseAl = (u32)__cvta_generic_to_shared(sAl);
    const u32 baseBh = (u32)__cvta_generic_to_shared(sBh);
    const u32 baseBl = (u32)__cvta_generic_to_shared(sBl);

    float acc[2][8][4];
    #pragma unroll
    for (int mi = 0; mi < 2; ++mi)
        #pragma unroll
        for (int ni = 0; ni < 8; ++ni)
            #pragma unroll
            for (int e = 0; e < 4; ++e) acc[mi][ni][e] = 0.f;

    #pragma unroll
    for (int ks = 0; ks < 4; ++ks) {
        const int ch = ks * 2 + (lq >> 1);
        u32 ah[2][4], al[2][4];
        #pragma unroll
        for (int mi = 0; mi < 2; ++mi) {
            int row = mw + mi * 16 + (lq & 1) * 8 + lr;
            u32 off = (u32)(row * 128 + ((ch ^ (row & 7)) << 4));
            ldsm4(ah[mi][0], ah[mi][1], ah[mi][2], ah[mi][3], baseAh + off);
            ldsm4(al[mi][0], al[mi][1], al[mi][2], al[mi][3], baseAl + off);
        }
        u32 bh[4][4], bl[4][4];
        #pragma unroll
        for (int nj = 0; nj < 4; ++nj) {
            int row = nw + nj * 16 + (lq & 1) * 8 + lr;
            u32 off = (u32)(row * 128 + ((ch ^ (row & 7)) << 4));
            ldsm4(bh[nj][0], bh[nj][1], bh[nj][2], bh[nj][3], baseBh + off);
            ldsm4(bl[nj][0], bl[nj][1], bl[nj][2], bl[nj][3], baseBl + off);
        }
        #pragma unroll
        for (int mi = 0; mi < 2; ++mi)
            #pragma unroll
            for (int ni = 0; ni < 8; ++ni) {
                int nj = ni >> 1;
                u32 h0 = (ni & 1) ? bh[nj][1] : bh[nj][0];
                u32 h1 = (ni & 1) ? bh[nj][3] : bh[nj][2];
                u32 l0 = (ni & 1) ? bl[nj][1] : bl[nj][0];
                u32 l1 = (ni & 1) ? bl[nj][3] : bl[nj][2];
                mma16816(acc[mi][ni], ah[mi], h0, h1);
                mma16816(acc[mi][ni], al[mi], h0, h1);
                mma16816(acc[mi][ni], ah[mi], l0, l1);
            }
    }

    // epilogue: C = max(sqa+sqb-dot, 0) quantized to u16 pairs
    const int tq = lane >> 2, tr = lane & 3;
    #pragma unroll
    for (int mi = 0; mi < 2; ++mi)
        #pragma unroll
        for (int rh = 0; rh < 2; ++rh) {
            int m = bi + mw + mi * 16 + rh * 8 + tq;
            float sa = sqa[m];
            #pragma unroll
            for (int ni = 0; ni < 8; ++ni) {
                int n = bj + nw + ni * 8 + tr * 2;
                float v0 = fmaxf(sa + sqb[n]     - acc[mi][ni][rh * 2 + 0], 0.f);
                float v1 = fmaxf(sa + sqb[n + 1] - acc[mi][ni][rh * 2 + 1], 0.f);
                u32 q0 = __float_as_uint(fmaf(v0, inv, 8388608.0f));
                u32 q1 = __float_as_uint(fmaf(v1, inv, 8388608.0f));
                *(u32*)(Cq + (u64)m * Nn + n) = __byte_perm(q0, q1, 0x5410);
            }
        }
}

// ---------------- merged tile softmin: all three matrices in ONE launch --------------
__global__ void __launch_bounds__(256, 3) tile_softmin_all_kernel(
    const uint4* __restrict__ Qxy, const uint4* __restrict__ Qxx, const uint4* __restrict__ Qyy,
    const float* __restrict__ faa, const float* __restrict__ gbb,
    const float* __restrict__ gab, const float* __restrict__ fba,
    const float* __restrict__ scales,
    const float* __restrict__ eps_ptr, float base_log, int init,
    float* __restrict__ pRM, float* __restrict__ pRS,
    float* __restrict__ pCM, float* __restrict__ pCS,
    float* __restrict__ pXM, float* __restrict__ pXS,
    float* __restrict__ pYM, float* __restrict__ pYS)
{
    int b = blockIdx.x;
    int which, bx, by;
    if (b < NCH * NCH) { which = 0; by = b >> 6; bx = b & 63; }
    else if (b < NCH * NCH + NTRI) { which = 1; tri_decode(b - NCH * NCH, by, bx); }
    else { which = 2; tri_decode(b - NCH * NCH - NTRI, by, bx); }

    const uint4* Q = (which == 0) ? Qxy : (which == 1) ? Qxx : Qyy;
    const float* potRow = (which == 0) ? gab : (which == 1) ? faa : gbb;
    const float* potCol = (which == 0) ? fba : (which == 1) ? faa : gbb;
    float* oRM = (which == 0) ? pRM : (which == 1) ? pXM : pYM;
    float* oRS = (which == 0) ? pRS : (which == 1) ? pXS : pYS;
    float* oCM = (which == 0) ? pCM : (which == 1) ? pXM : pYM;
    float* oCS = (which == 0) ? pCS : (which == 1) ? pXS : pYS;
    const bool doCol = (which == 0) || (by > bx);

    const int tid = threadIdx.x;
    const int c16 = tid & 15, rp = tid >> 4;

    const float s2   = L2E / (*eps_ptr);
    const float b2   = base_log * L2E;
    const float scs2 = scales[which] * s2;
    const float off  = b2 + 8388608.0f * scs2;

    __shared__ float gp[128];
    __shared__ float fp[128];
    __shared__ float2 part[128 * 17];

    uint4 qv[8];
    #pragma unroll
    for (int p = 0; p < 8; ++p)
        qv[p] = __ldcs(&Q[(u64)(by * 128 + rp + 16 * p) * 1024 + bx * 16 + c16]);

    if (tid < 128) {
        float pv = init ? 0.f : potRow[bx * 128 + tid];
        gp[tid] = fmaf(pv, s2, off);
    } else {
        int t = tid - 128;
        float pv = init ? 0.f : potCol[by * 128 + t];
        fp[t] = fmaf(pv, s2, off);
    }
    __syncthreads();

    float4 gA = *(const float4*)&gp[c16 * 8];
    float4 gB = *(const float4*)&gp[c16 * 8 + 4];
    float fpv[8];
    #pragma unroll
    for (int p = 0; p < 8; ++p) fpv[p] = fp[rp + 16 * p];

    const float nscs2 = -scs2;

    #pragma unroll
    for (int p = 0; p < 8; ++p) {
        float v0 = fmaf(q2f_lo(qv[p].x), nscs2, gA.x);
        float v1 = fmaf(q2f_hi(qv[p].x), nscs2, gA.y);
        float v2 = fmaf(q2f_lo(qv[p].y), nscs2, gA.z);
        float v3 = fmaf(q2f_hi(qv[p].y), nscs2, gA.w);
        float v4 = fmaf(q2f_lo(qv[p].z), nscs2, gB.x);
        float v5 = fmaf(q2f_hi(qv[p].z), nscs2, gB.y);
        float v6 = fmaf(q2f_lo(qv[p].w), nscs2, gB.z);
        float v7 = fmaf(q2f_hi(qv[p].w), nscs2, gB.w);
        float m = fmaxf(fmaxf(fmaxf(v0, v1), fmaxf(v2, v3)),
                        fmaxf(fmaxf(v4, v5), fmaxf(v6, v7)));
        float s = ((ex2(v0 - m) + ex2(v1 - m)) + (ex2(v2 - m) + ex2(v3 - m)))
                + ((ex2(v4 - m) + ex2(v5 - m)) + (ex2(v6 - m) + ex2(v7 - m)));
        part[(rp + 16 * p) * 17 + c16] = make_float2(m, s);
    }
    __syncthreads();

    if (tid < 128) {
        float M = -3.4e38f;
        float2 pr[16];
        #pragma unroll
        for (int k = 0; k < 16; ++k) { pr[k] = part[tid * 17 + k]; M = fmaxf(M, pr[k].x); }
        float S = 0.f;
        #pragma unroll
        for (int k = 0; k < 16; ++k) S += pr[k].y * ex2(pr[k].x - M);
        u64 oidx = (u64)bx * Nn + by * 128 + tid;
        oRM[oidx] = M;
        oRS[oidx] = S;
    }

    if (doCol) {
        __syncthreads();
        #pragma unroll
        for (int e = 0; e < 8; ++e) {
            float v[8];
            #pragma unroll
            for (int p = 0; p < 8; ++p) {
                u32 a = (e < 2) ? qv[p].x : (e < 4) ? qv[p].y : (e < 6) ? qv[p].z : qv[p].w;
                float fq = (e & 1) ? q2f_hi(a) : q2f_lo(a);
                v[p] = fmaf(fq, nscs2, fpv[p]);
            }
            float m = fmaxf(fmaxf(fmaxf(v[0], v[1]), fmaxf(v[2], v[3])),
                            fmaxf(fmaxf(v[4], v[5]), fmaxf(v[6], v[7])));
            float s = ((ex2(v[0] - m) + ex2(v[1] - m)) + (ex2(v[2] - m) + ex2(v[3] - m)))
                    + ((ex2(v[4] - m) + ex2(v[5] - m)) + (ex2(v[6] - m) + ex2(v[7] - m)));
            part[(rp * 8 + e) * 17 + c16] = make_float2(m, s);
        }
        __syncthreads();
        if (tid < 128) {
            int e = tid & 7, cc = tid >> 3;    // col = cc*8 + e
            float M = -3.4e38f;
            float2 pc[16];
            #pragma unroll
            for (int k = 0; k < 16; ++k) {
                pc[k] = part[(k * 8 + e) * 17 + cc];
                M = fmaxf(M, pc[k].x);
            }
            float S = 0.f;
            #pragma unroll
            for (int k = 0; k < 16; ++k) S += pc[k].y * ex2(pc[k].x - M);
            int col = cc * 8 + e;
            u64 oidx = (u64)by * Nn + bx * 128 + col;
            oCM[oidx] = M;
            oCS[oidx] = S;
        }
    }
}

// ---------------- combine: one output per thread, 32768 threads ----------------
__global__ void __launch_bounds__(256) combine_update_kernel(
    const float* __restrict__ pRM, const float* __restrict__ pRS,
    const float* __restrict__ pCM, const float* __restrict__ pCS,
    const float* __restrict__ pXM, const float* __restrict__ pXS,
    const float* __restrict__ pYM, const float* __restrict__ pYS,
    const float* __restrict__ eps_ptr, int mode,
    float* __restrict__ faa, float* __restrict__ gbb,
    float* __restrict__ gab, float* __restrict__ fba,
    float* __restrict__ tft, float* __restrict__ tgt,
    float* __restrict__ tftaa, float* __restrict__ tgtbb)
{
    const int gid = blockIdx.x * 256 + threadIdx.x;   // 0..32767
    const int p = gid >> 13;
    const int i = gid & 8191;
    const float eps = *eps_ptr;
    const float sc = -eps * LN2;

    const float* pM = (p == 0) ? pRM : (p == 1) ? pCM : (p == 2) ? pXM : pYM;
    const float* pS = (p == 0) ? pRS : (p == 1) ? pCS : (p == 2) ? pXS : pYS;

    float M = -3.4e38f;
    #pragma unroll 16
    for (int c = 0; c < NCH; ++c) M = fmaxf(M, pM[(u64)c * Nn + i]);
    float S = 0.f;
    #pragma unroll 16
    for (int c = 0; c < NCH; ++c) S += pS[(u64)c * Nn + i] * ex2(pM[(u64)c * Nn + i] - M);
    float v = sc * (lg2(S) + M);

    float* dstA = (p == 0) ? fba : (p == 1) ? gab : (p == 2) ? faa : gbb;
    float* dstT = (p == 0) ? tft : (p == 1) ? tgt : (p == 2) ? tftaa : tgtbb;

    if (mode == 0)       dstA[i] = v;
    else if (mode == 1)  dstA[i] = 0.5f * (dstA[i] + v);
    else                 dstT[i] = v;
}

// ---------------- final scalar ----------------
__global__ void final_kernel(const float* __restrict__ fbaf, const float* __restrict__ faaf,
                             const float* __restrict__ gabf, const float* __restrict__ gbbf,
                             float* __restrict__ out)
{
    __shared__ float red[32];
    int tid = threadIdx.x;
    int lane = tid & 31, wid = tid >> 5;
    float s = 0.f;
    for (int i = tid; i < Nn; i += 1024)
        s += (fbaf[i] - faaf[i]) + (gabf[i] - gbbf[i]);
    #pragma unroll
    for (int o = 16; o; o >>= 1) s += __shfl_xor_sync(0xffffffffu, s, o);
    if (lane == 0) red[wid] = s;
    __syncthreads();
    if (wid == 0) {
        float v = red[lane];
        #pragma unroll
        for (int o = 16; o; o >>= 1) v += __shfl_xor_sync(0xffffffffu, v, o);
        if (lane == 0) out[0] = v / (float)Nn;
    }
}

// ---------------- launch ----------------
extern "C" void kernel_launch(void* const* d_in, const int* in_sizes, int n_in,
                              void* d_out, int out_size)
{
    const float* X   = (const float*)d_in[0];
    const float* Y   = (const float*)d_in[1];
    const float* eps = (const float*)d_in[2];
    const int n_eps  = in_sizes[2];
    float* out = (float*)d_out;

    u16 *Cxy, *Cxx, *Cyy;
    __nv_bfloat16 *Xh, *Xl, *Yh, *Yl;
    float *sqx, *sqy, *scales;
    float *faa, *gbb, *gab, *fba, *tft, *tgt, *tftaa, *tgtbb;
    float *pRM, *pRS, *pCM, *pCS, *pXM, *pXS, *pYM, *pYS;
    cudaGetSymbolAddress((void**)&Cxy, d_Cxy);
    cudaGetSymbolAddress((void**)&Cxx, d_Cxx);
    cudaGetSymbolAddress((void**)&Cyy, d_Cyy);
    cudaGetSymbolAddress((void**)&Xh, d_Xh);
    cudaGetSymbolAddress((void**)&Xl, d_Xl);
    cudaGetSymbolAddress((void**)&Yh, d_Yh);
    cudaGetSymbolAddress((void**)&Yl, d_Yl);
    cudaGetSymbolAddress((void**)&sqx, d_sqx);
    cudaGetSymbolAddress((void**)&sqy, d_sqy);
    cudaGetSymbolAddress((void**)&scales, d_scales);
    cudaGetSymbolAddress((void**)&faa, d_faa);
    cudaGetSymbolAddress((void**)&gbb, d_gbb);
    cudaGetSymbolAddress((void**)&gab, d_gab);
    cudaGetSymbolAddress((void**)&fba, d_fba);
    cudaGetSymbolAddress((void**)&tft, d_tft);
    cudaGetSymbolAddress((void**)&tgt, d_tgt);
    cudaGetSymbolAddress((void**)&tftaa, d_tftaa);
    cudaGetSymbolAddress((void**)&tgtbb, d_tgtbb);
    cudaGetSymbolAddress((void**)&pRM, d_pRM);
    cudaGetSymbolAddress((void**)&pRS, d_pRS);
    cudaGetSymbolAddress((void**)&pCM, d_pCM);
    cudaGetSymbolAddress((void**)&pCS, d_pCS);
    cudaGetSymbolAddress((void**)&pXM, d_pXM);
    cudaGetSymbolAddress((void**)&pXS, d_pXS);
    cudaGetSymbolAddress((void**)&pYM, d_pYM);
    cudaGetSymbolAddress((void**)&pYS, d_pYS);

    cudaFuncSetAttribute(mma_cost_gemm_kernel,
                         cudaFuncAttributeMaxDynamicSharedMemorySize, 65536);

    const float LOGW = -logf((float)Nn);
    dim3 gg(NCH, NCH);

    sqnorm_kernel<<<1024, 256>>>(X, sqx);
    sqnorm_kernel<<<1024, 256>>>(Y, sqy);
    split_kernel<<<2048, 256>>>(X, Xh, Xl);
    split_kernel<<<2048, 256>>>(Y, Yh, Yl);
    scale_kernel<<<1, 256>>>(sqx, sqy, scales);
    mma_cost_gemm_kernel<<<gg, 256, 65536>>>(Xh, Xl, Yh, Yl, sqx, sqy, scales + 3, Cxy, 0);
    mma_cost_gemm_kernel<<<NTRI, 256, 65536>>>(Xh, Xl, Xh, Xl, sqx, sqx, scales + 4, Cxx, 1);
    mma_cost_gemm_kernel<<<NTRI, 256, 65536>>>(Yh, Yl, Yh, Yl, sqy, sqy, scales + 5, Cyy, 1);

    for (int k = -1; k <= n_eps; ++k) {
        const float* ek = (k < 0) ? eps : (k < n_eps ? eps + k : eps + (n_eps - 1));
        int mode = (k < 0) ? 0 : (k < n_eps ? 1 : 2);
        int init = (k < 0) ? 1 : 0;
        tile_softmin_all_kernel<<<NBLK, 256>>>(
            (const uint4*)Cxy, (const uint4*)Cxx, (const uint4*)Cyy,
            faa, gbb, gab, fba, scales, ek, LOGW, init,
            pRM, pRS, pCM, pCS, pXM, pXS, pYM, pYS);
        combine_update_kernel<<<128, 256>>>(
            pRM, pRS, pCM, pCS, pXM, pXS, pYM, pYS, ek, mode,
            faa, gbb, gab, fba, tft, tgt, tftaa, tgtbb);
    }

    final_kernel<<<1, 1024>>>(tft, tftaa, tgt, tgtbb, out);
}